// round 10
// baseline (speedup 1.0000x reference)
#include <cuda_runtime.h>
#include <cuda_fp16.h>
#include <math.h>
#include <stdint.h>

#define H 128
#define LYR 4
#define G 64
#define C 10
#define MAXN 50048
#define MAXE 600064
#define EPSV 1e-5f
#define LO_SCALE 1024.0f
#define INV_LO (1.0f / 1024.0f)

// Persistent device scratch (static, no allocation).
// INVARIANT: g_deg, g_pool, g_stats are zero at entry (zero-initialized .bss;
// restored to zero by pool_kernel / head_kernel at the end of every call).
__device__ __align__(16) float g_h[MAXN * H];
__device__ __align__(16) float g_m[MAXN * H];
__device__ __align__(16) float g_pre[MAXN * H];
__device__ __align__(16) float g_a[MAXN * 2];
__device__ __align__(16) float g_stats[LYR * 2 * H];
__device__ __align__(16) float g_pool[G * H];
__device__ int g_deg[MAXN];
__device__ int g_off[MAXN];
__device__ int g_cursor[MAXN];
__device__ int g_adj[MAXE];          // src node per CSR slot
__device__ int g_btot[32];
// 9 matrices, each: hi half (64*136 words) + lo half (64*136 words), fp16x2
#define SROW 136
#define HALF_WORDS (64 * SROW)                // 8704 words (one 128x128 f16 image)
#define BMAT_WORDS (2 * HALF_WORDS)
__device__ __align__(16) uint32_t g_Bsplit[9 * BMAT_WORDS];

static inline int cdiv(int a, int b) { return (a + b - 1) / b; }

// ---------------------------------------------------------------------------
// fp16 helpers
// ---------------------------------------------------------------------------
__device__ __forceinline__ uint32_t pack_h2(float f0, float f1) {
    __half2 h = __floats2half2_rn(f0, f1);
    return *(uint32_t*)&h;
}

__device__ __forceinline__ void mma16816(float* d, const uint32_t* a,
                                         const uint32_t* b) {
    asm volatile(
        "mma.sync.aligned.m16n8k16.row.col.f32.f16.f16.f32 "
        "{%0,%1,%2,%3}, {%4,%5,%6,%7}, {%8,%9}, {%0,%1,%2,%3};\n"
        : "+f"(d[0]), "+f"(d[1]), "+f"(d[2]), "+f"(d[3])
        : "r"(a[0]), "r"(a[1]), "r"(a[2]), "r"(a[3]),
          "r"(b[0]), "r"(b[1]));
}

// ---------------------------------------------------------------------------
// Prep: split weight matrices (B = W^T) into fp16 hi + scaled-lo images.
// Image layout: word kp*136 + n (kp = k-pair, n = output col).
// ---------------------------------------------------------------------------
__global__ __launch_bounds__(256) void prep_kernel(
    const float* __restrict__ W_in, const float* __restrict__ Wm,
    const float* __restrict__ Wr)
{
    int mat = blockIdx.y;
    const float* W = (mat == 0) ? W_in
                   : (mat < 5) ? Wm + (mat - 1) * H * H
                               : Wr + (mat - 5) * H * H;
    uint32_t* out = g_Bsplit + mat * BMAT_WORDS;
    int p = blockIdx.x * 256 + threadIdx.x;
    int n = p >> 6;
    int kp = p & 63;
    int k = kp * 2;
    float f0 = W[k * H + n];
    float f1 = W[(k + 1) * H + n];
    __half h0 = __float2half_rn(f0);
    __half h1 = __float2half_rn(f1);
    float r0 = (f0 - __half2float(h0)) * LO_SCALE;
    float r1 = (f1 - __half2float(h1)) * LO_SCALE;
    out[kp * SROW + n] = pack_h2(__half2float(h0), __half2float(h1));
    out[HALF_WORDS + kp * SROW + n] = pack_h2(r0, r1);
}

// ---------------------------------------------------------------------------
// GEMM building blocks (fp16, A single image, B hi+lo with scaled lo)
// ---------------------------------------------------------------------------
#define PERS1_SMEM (3 * HALF_WORDS * 4)       // 104448 B (A + one B pair)
#define PERS2_SMEM (5 * HALF_WORDS * 4)       // 174080 B (A + two B pairs)
#define GRID_PERS 148

__device__ __forceinline__ void gemm_copyB(uint32_t* dstB, const uint32_t* Bimg,
                                           int tid) {
    uint4* bs = (uint4*)dstB;
    const uint4* bg = (const uint4*)Bimg;
#pragma unroll
    for (int i = 0; i < 17; i++)
        bs[tid + i * 256] = bg[tid + i * 256];
}

// Convert A tile (raw fp32, optional affine LN + relu) to fp16 image;
// fused adot partials.
__device__ __forceinline__ void gemm_cvtA(uint32_t* Ah, const float* Araw,
    int M, int rowBase, int tid,
    const float* s_scale, const float* s_shift,
    const float* s_ws, const float* s_wd,
    float (*s_pdS)[128], float (*s_pdD)[128])
{
    int row = tid & 127;
    int khalf = tid >> 7;
    bool ok = (rowBase + row) < M;
    const float4* Ar = (const float4*)(Araw + (size_t)(rowBase + row) * 128 + khalf * 64);
    float ss = 0.f, sd = 0.f;
#pragma unroll
    for (int i = 0; i < 16; i++) {
        float4 p = ok ? Ar[i] : make_float4(0.f, 0.f, 0.f, 0.f);
        int k = khalf * 64 + i * 4;
        float4 v;
        v.x = fmaxf(p.x * s_scale[k + 0] + s_shift[k + 0], 0.f);
        v.y = fmaxf(p.y * s_scale[k + 1] + s_shift[k + 1], 0.f);
        v.z = fmaxf(p.z * s_scale[k + 2] + s_shift[k + 2], 0.f);
        v.w = fmaxf(p.w * s_scale[k + 3] + s_shift[k + 3], 0.f);
        if (!ok) { v.x = 0.f; v.y = 0.f; v.z = 0.f; v.w = 0.f; }
        ss += v.x * s_ws[k] + v.y * s_ws[k + 1] + v.z * s_ws[k + 2] + v.w * s_ws[k + 3];
        sd += v.x * s_wd[k] + v.y * s_wd[k + 1] + v.z * s_wd[k + 2] + v.w * s_wd[k + 3];
        int kp = khalf * 32 + i * 2;
        Ah[kp * SROW + row]       = pack_h2(v.x, v.y);
        Ah[(kp + 1) * SROW + row] = pack_h2(v.z, v.w);
    }
    s_pdS[khalf][row] = ss;
    s_pdD[khalf][row] = sd;
}

// Plain convert (no LN, no adot) for the input GEMM
__device__ __forceinline__ void gemm_cvtA_plain(uint32_t* Ah, const float* Araw,
                                                int M, int rowBase, int tid)
{
    int row = tid & 127;
    int khalf = tid >> 7;
    bool ok = (rowBase + row) < M;
    const float4* Ar = (const float4*)(Araw + (size_t)(rowBase + row) * 128 + khalf * 64);
#pragma unroll
    for (int i = 0; i < 16; i++) {
        float4 v = ok ? Ar[i] : make_float4(0.f, 0.f, 0.f, 0.f);
        int kp = khalf * 32 + i * 2;
        Ah[kp * SROW + row]       = pack_h2(v.x, v.y);
        Ah[(kp + 1) * SROW + row] = pack_h2(v.z, v.w);
    }
}

// Two-accumulator compute: acc += A*B_hi ; accLo += A*B_lo (B_lo pre-scaled)
__device__ __forceinline__ void gemm_compute(const uint32_t* Ah,
    const uint32_t* Bb, int warp_m, int warp_n, int g, int tg,
    float acc[2][8][4], float accLo[2][8][4])
{
#pragma unroll
    for (int mi = 0; mi < 2; mi++)
#pragma unroll
        for (int ni = 0; ni < 8; ni++)
#pragma unroll
            for (int q = 0; q < 4; q++) { acc[mi][ni][q] = 0.f; accLo[mi][ni][q] = 0.f; }

#pragma unroll
    for (int s = 0; s < 8; s++) {
        int q0 = s * 8 + tg;
        int q1 = s * 8 + 4 + tg;
        uint32_t a[2][4];
#pragma unroll
        for (int mi = 0; mi < 2; mi++) {
            int r0 = warp_m + mi * 16 + g;
            a[mi][0] = Ah[q0 * SROW + r0];
            a[mi][1] = Ah[q0 * SROW + r0 + 8];
            a[mi][2] = Ah[q1 * SROW + r0];
            a[mi][3] = Ah[q1 * SROW + r0 + 8];
        }
#pragma unroll
        for (int ni = 0; ni < 8; ni++) {
            int cn = warp_n + ni * 8 + g;
            uint32_t bhi[2], blo[2];
            bhi[0] = Bb[q0 * SROW + cn];
            bhi[1] = Bb[q1 * SROW + cn];
            blo[0] = Bb[HALF_WORDS + q0 * SROW + cn];
            blo[1] = Bb[HALF_WORDS + q1 * SROW + cn];
#pragma unroll
            for (int mi = 0; mi < 2; mi++) {
                mma16816(acc[mi][ni], a[mi], bhi);
                mma16816(accLo[mi][ni], a[mi], blo);
            }
        }
    }
}

__device__ __forceinline__ void gemm_store(float acc[2][8][4], float accLo[2][8][4],
    const float* __restrict__ bias, float* __restrict__ Cm,
    int M, int rowBase, int warp_m, int warp_n, int g, int tg, int relu)
{
    float bv[8][2];
#pragma unroll
    for (int ni = 0; ni < 8; ni++) {
        int cb = warp_n + ni * 8 + 2 * tg;
        bv[ni][0] = bias[cb];
        bv[ni][1] = bias[cb + 1];
    }
#pragma unroll
    for (int mi = 0; mi < 2; mi++) {
#pragma unroll
        for (int rh = 0; rh < 2; rh++) {
            int row = rowBase + warp_m + mi * 16 + g + rh * 8;
            if (row < M) {
#pragma unroll
                for (int ni = 0; ni < 8; ni++) {
                    float vx = acc[mi][ni][rh * 2 + 0] + accLo[mi][ni][rh * 2 + 0] * INV_LO + bv[ni][0];
                    float vy = acc[mi][ni][rh * 2 + 1] + accLo[mi][ni][rh * 2 + 1] * INV_LO + bv[ni][1];
                    if (relu) { vx = fmaxf(vx, 0.f); vy = fmaxf(vy, 0.f); }
                    float2 o; o.x = vx; o.y = vy;
                    *(float2*)(Cm + (size_t)row * 128 + warp_n + ni * 8 + 2 * tg) = o;
                }
            }
        }
    }
}

// Persistent single GEMM (input layer): C = relu(A @ W + b). B copied once.
__global__ __launch_bounds__(256) void pers_gemm(
    int M, const float* __restrict__ A, const uint32_t* __restrict__ Bimg,
    const float* __restrict__ bias, float* __restrict__ Cm, int relu)
{
    extern __shared__ uint32_t sm[];
    uint32_t* Ah = sm;
    uint32_t* Bb = sm + HALF_WORDS;

    int tid = threadIdx.x;
    int warp = tid >> 5, lane = tid & 31;
    int g = lane >> 2, tg = lane & 3;
    int warp_m = (warp >> 1) * 32;
    int warp_n = (warp & 1) * 64;
    int ntiles = (M + 127) >> 7;

    gemm_copyB(Bb, Bimg, tid);

    for (int tile = blockIdx.x; tile < ntiles; tile += gridDim.x) {
        __syncthreads();
        gemm_cvtA_plain(Ah, A, M, tile * 128, tid);
        __syncthreads();
        float acc[2][8][4], accLo[2][8][4];
        gemm_compute(Ah, Bb, warp_m, warp_n, g, tg, acc, accLo);
        gemm_store(acc, accLo, bias, Cm, M, tile * 128, warp_m, warp_n, g, tg, relu);
    }
}

// ---------------------------------------------------------------------------
// Persistent dual GEMM with fused input-normalization and adot.
// A_eff[r][c] = relu(Araw[r][c] * scale[c] + shift[c])  (affine LN or identity)
// Outputs: m = A_eff@Wm + bm ; pre = A_eff@Wr + br ; a[r] = A_eff[r]·(ws|wd).
// In-place Araw == pre output is safe (tile ownership is exclusive).
// ---------------------------------------------------------------------------
__global__ __launch_bounds__(256) void pers_dual_gemm(
    int M, float invN, const float* __restrict__ Araw, int useLN,
    const float* __restrict__ stats,
    const float* __restrict__ gamma, const float* __restrict__ beta,
    const float* __restrict__ Wa_l, float* __restrict__ a_out,
    const uint32_t* __restrict__ Bm_img, const uint32_t* __restrict__ Br_img,
    const float* __restrict__ bm, const float* __restrict__ br,
    float* __restrict__ Cm, float* __restrict__ Cpre)
{
    extern __shared__ uint32_t sm[];
    uint32_t* Ah  = sm;
    uint32_t* Bmb = sm + HALF_WORDS;
    uint32_t* Brb = sm + 3 * HALF_WORDS;
    __shared__ float s_scale[128], s_shift[128];
    __shared__ float s_ws[128], s_wd[128];
    __shared__ float s_pdS[2][128], s_pdD[2][128];

    int tid = threadIdx.x;
    int warp = tid >> 5, lane = tid & 31;
    int g = lane >> 2, tg = lane & 3;
    int warp_m = (warp >> 1) * 32;
    int warp_n = (warp & 1) * 64;
    int ntiles = (M + 127) >> 7;

    if (tid < 128) {
        float sc = 1.f, sh = 0.f;
        if (useLN) {
            float s = stats[tid], q = stats[128 + tid];
            float mu = s * invN;
            float var = q * invN - mu * mu;
            float rs = rsqrtf(var + EPSV);
            sc = rs * gamma[tid];
            sh = beta[tid] - mu * sc;
        }
        s_scale[tid] = sc;
        s_shift[tid] = sh;
        s_ws[tid] = Wa_l[tid];
        s_wd[tid] = Wa_l[128 + tid];
    }
    gemm_copyB(Bmb, Bm_img, tid);
    gemm_copyB(Brb, Br_img, tid);

    for (int tile = blockIdx.x; tile < ntiles; tile += gridDim.x) {
        int rowBase = tile * 128;
        __syncthreads();   // B/scale ready; prev iter compute + a_out done
        gemm_cvtA(Ah, Araw, M, rowBase, tid, s_scale, s_shift, s_ws, s_wd,
                  s_pdS, s_pdD);
        __syncthreads();
        if (tid < 128 && rowBase + tid < M) {
            a_out[2 * (rowBase + tid)]     = s_pdS[0][tid] + s_pdS[1][tid];
            a_out[2 * (rowBase + tid) + 1] = s_pdD[0][tid] + s_pdD[1][tid];
        }
        {
            float acc[2][8][4], accLo[2][8][4];
            gemm_compute(Ah, Bmb, warp_m, warp_n, g, tg, acc, accLo);
            gemm_store(acc, accLo, bm, Cm, M, rowBase, warp_m, warp_n, g, tg, 0);
        }
        {
            float acc[2][8][4], accLo[2][8][4];
            gemm_compute(Ah, Brb, warp_m, warp_n, g, tg, acc, accLo);
            gemm_store(acc, accLo, br, Cpre, M, rowBase, warp_m, warp_n, g, tg, 0);
        }
    }
}

// ---------------------------------------------------------------------------
// CSR build: count (g_deg is zero at entry by invariant), scan, fill
// ---------------------------------------------------------------------------
__global__ __launch_bounds__(256) void count_kernel(int E, const int* __restrict__ dst) {
    int i = blockIdx.x * 256 + threadIdx.x;
    if (i < E) atomicAdd(&g_deg[dst[i]], 1);
}

#define SCB 4096   // elements per scan block (256 thr x 16)

__global__ __launch_bounds__(256) void scan1_kernel(int N) {
    __shared__ int wsum[8];
    int tid = threadIdx.x;
    int lane = tid & 31, w = tid >> 5;
    int base = blockIdx.x * SCB + tid * 16;
    int v[16];
    int s = 0;
#pragma unroll
    for (int i = 0; i < 16; i++) {
        int idx = base + i;
        v[i] = (idx < N) ? g_deg[idx] : 0;
        s += v[i];
    }
    int incl = s;
#pragma unroll
    for (int d = 1; d < 32; d <<= 1) {
        int t = __shfl_up_sync(0xFFFFFFFFu, incl, d);
        if (lane >= d) incl += t;
    }
    if (lane == 31) wsum[w] = incl;
    __syncthreads();
    if (tid == 0) {
        int c = 0;
#pragma unroll
        for (int i = 0; i < 8; i++) { int x = wsum[i]; wsum[i] = c; c += x; }
        g_btot[blockIdx.x] = c;
    }
    __syncthreads();
    int run = incl - s + wsum[w];
#pragma unroll
    for (int i = 0; i < 16; i++) {
        int idx = base + i;
        if (idx < N) g_off[idx] = run;
        run += v[i];
    }
}

// scan3: adds inline prefix of block totals (nb <= 13)
__global__ __launch_bounds__(256) void scan3_kernel(int N) {
    int i = blockIdx.x * 256 + threadIdx.x;
    if (i < N) {
        int b = i / SCB;
        int add = 0;
        for (int j = 0; j < b; j++) add += g_btot[j];
        int o = g_off[i] + add;
        g_off[i] = o;
        g_cursor[i] = o;
    }
}

__global__ __launch_bounds__(256) void fill_kernel(
    int E, const int* __restrict__ src, const int* __restrict__ dst)
{
    int i = blockIdx.x * 256 + threadIdx.x;
    if (i < E) {
        int slot = atomicAdd(&g_cursor[dst[i]], 1);
        g_adj[slot] = src[i];
    }
}

// ---------------------------------------------------------------------------
// Gather: pre[d] += sum_in sigmoid(a_src[s]+a_dst[d]+ba)*m[s]
// CSR, warp per row, 1-deep prefetch of (m row, a_src). Fused LN stats.
// ---------------------------------------------------------------------------
__global__ __launch_bounds__(256) void gather_kernel(
    int N, const float* __restrict__ a, const float* __restrict__ ba_l,
    const float* __restrict__ m, float* __restrict__ pre,
    float* __restrict__ stats)
{
    __shared__ float redS[8][128], redQ[8][128];
    int tid = threadIdx.x;
    int w = tid >> 5, lane = tid & 31;
    float bav = ba_l[0];
    float4 s1 = make_float4(0.f, 0.f, 0.f, 0.f);
    float4 s2 = make_float4(0.f, 0.f, 0.f, 0.f);
    const float4* m4 = (const float4*)m;

    for (int row = blockIdx.x * 8 + w; row < N; row += gridDim.x * 8) {
        float4 v = ((const float4*)pre)[row * 32 + lane];
        float ad = a[2 * row + 1] + bav;
        int off = g_off[row];
        int deg = g_deg[row];
        const int* ep = g_adj + off;
        if (deg > 0) {
            int s0 = ep[0];
            float4 mv_n = m4[(size_t)s0 * 32 + lane];
            float z_n = a[2 * s0];
            for (int e = 0; e < deg; e++) {
                float4 mv = mv_n;
                float z = z_n + ad;
                if (e + 1 < deg) {
                    int sn = ep[e + 1];
                    mv_n = m4[(size_t)sn * 32 + lane];
                    z_n = a[2 * sn];
                }
                float gate = 1.f / (1.f + __expf(-z));
                v.x += gate * mv.x; v.y += gate * mv.y;
                v.z += gate * mv.z; v.w += gate * mv.w;
            }
        }
        ((float4*)pre)[row * 32 + lane] = v;
        s1.x += v.x; s1.y += v.y; s1.z += v.z; s1.w += v.w;
        s2.x += v.x * v.x; s2.y += v.y * v.y;
        s2.z += v.z * v.z; s2.w += v.w * v.w;
    }
    *(float4*)&redS[w][lane * 4] = s1;
    *(float4*)&redQ[w][lane * 4] = s2;
    __syncthreads();
    if (tid < 128) {
        float aa = 0.f, bb = 0.f;
#pragma unroll
        for (int i = 0; i < 8; i++) { aa += redS[i][tid]; bb += redQ[i][tid]; }
        atomicAdd(&stats[tid], aa);
        atomicAdd(&stats[128 + tid], bb);
    }
}

// ---------------------------------------------------------------------------
// Final pool: normalize pre (layer 3) on the fly and pool. Warp per row.
// Also restores g_deg = 0 (state invariant for the next call).
// ---------------------------------------------------------------------------
__global__ __launch_bounds__(256) void pool_kernel(
    int N, float invN, const float* __restrict__ pre,
    const float* __restrict__ stats,
    const float* __restrict__ gamma, const float* __restrict__ beta,
    const int* __restrict__ batch, float* __restrict__ pool)
{
    int tid = threadIdx.x;
    int w = tid >> 5, lane = tid & 31;
    float sc[4], sh[4];
#pragma unroll
    for (int i = 0; i < 4; i++) {
        int c = lane * 4 + i;
        float s = stats[c], q = stats[128 + c];
        float mu = s * invN;
        float var = q * invN - mu * mu;
        float rs = rsqrtf(var + EPSV);
        sc[i] = rs * gamma[c];
        sh[i] = beta[c] - mu * sc[i];
    }
    for (int row = blockIdx.x * 8 + w; row < N; row += gridDim.x * 8) {
        float4 p = ((const float4*)pre)[row * 32 + lane];
        float4 v;
        v.x = fmaxf(p.x * sc[0] + sh[0], 0.f);
        v.y = fmaxf(p.y * sc[1] + sh[1], 0.f);
        v.z = fmaxf(p.z * sc[2] + sh[2], 0.f);
        v.w = fmaxf(p.w * sc[3] + sh[3], 0.f);
        int b = batch[row];
        atomicAdd(((float4*)(pool + (size_t)b * 128)) + lane, v);
        if (lane == 0) g_deg[row] = 0;     // restore invariant
    }
}

// ---------------------------------------------------------------------------
// MLP head; restores g_pool and g_stats to zero (state invariant).
// ---------------------------------------------------------------------------
__global__ __launch_bounds__(256) void head_kernel(
    float* __restrict__ pool,
    const float* __restrict__ W1, const float* __restrict__ b1,
    const float* __restrict__ W2, const float* __restrict__ b2,
    float* __restrict__ out, float* __restrict__ stats)
{
    __shared__ float sh[G * 64];
    int tid = threadIdx.x;
    for (int o = tid; o < G * 64; o += 256) {
        int g = o >> 6, j = o & 63;
        float s = b1[j];
        const float* pr = pool + g * 128;
#pragma unroll 4
        for (int k = 0; k < 128; k++) s += pr[k] * W1[k * 64 + j];
        sh[o] = fmaxf(s, 0.f);
    }
    __syncthreads();            // all reads of pool complete
    for (int o = tid; o < G * H; o += 256) pool[o] = 0.f;
    for (int o = tid; o < LYR * 2 * H; o += 256) stats[o] = 0.f;
    for (int o = tid; o < G * C; o += 256) {
        int g = o / C, c = o % C;
        float s = b2[c];
        const float* hr = sh + g * 64;
#pragma unroll 4
        for (int k = 0; k < 64; k++) s += hr[k] * W2[k * C + c];
        out[o] = s * 0.5f;   // /TEMP
    }
}

// ---------------------------------------------------------------------------
// Launch
// ---------------------------------------------------------------------------
extern "C" void kernel_launch(void* const* d_in, const int* in_sizes, int n_in,
                              void* d_out, int out_size)
{
    const float* x     = (const float*)d_in[0];
    const int*   ei    = (const int*)d_in[1];
    const int*   batch = (const int*)d_in[2];
    const float* W_in  = (const float*)d_in[3];
    const float* b_in  = (const float*)d_in[4];
    const float* Wa    = (const float*)d_in[5];
    const float* ba    = (const float*)d_in[6];
    const float* Wm    = (const float*)d_in[7];
    const float* bm    = (const float*)d_in[8];
    const float* Wr    = (const float*)d_in[9];
    const float* br    = (const float*)d_in[10];
    const float* gamma = (const float*)d_in[11];
    const float* beta  = (const float*)d_in[12];
    const float* W1    = (const float*)d_in[13];
    const float* b1    = (const float*)d_in[14];
    const float* W2    = (const float*)d_in[15];
    const float* b2    = (const float*)d_in[16];

    int N = in_sizes[0] / 128;
    int E = in_sizes[1] / 2;
    const int* src = ei;
    const int* dst = ei + E;

    cudaFuncSetAttribute(pers_gemm, cudaFuncAttributeMaxDynamicSharedMemorySize,
                         PERS1_SMEM);
    cudaFuncSetAttribute(pers_dual_gemm, cudaFuncAttributeMaxDynamicSharedMemorySize,
                         PERS2_SMEM);

    float *p_h, *p_m, *p_pre, *p_a, *p_pool, *p_stats;
    uint32_t* p_B;
    cudaGetSymbolAddress((void**)&p_h, g_h);
    cudaGetSymbolAddress((void**)&p_m, g_m);
    cudaGetSymbolAddress((void**)&p_pre, g_pre);
    cudaGetSymbolAddress((void**)&p_a, g_a);
    cudaGetSymbolAddress((void**)&p_pool, g_pool);
    cudaGetSymbolAddress((void**)&p_stats, g_stats);
    cudaGetSymbolAddress((void**)&p_B, g_Bsplit);

    int rowBlocks = cdiv(N, 8);
    int scanBlocks = cdiv(N, SCB);
    float invN = 1.0f / (float)N;

    // --- one-time per call: weights prep + CSR build (g_deg zero by invariant)
    prep_kernel<<<dim3(32, 9), 256>>>(W_in, Wm, Wr);
    count_kernel<<<cdiv(E, 256), 256>>>(E, dst);
    scan1_kernel<<<scanBlocks, 256>>>(N);
    scan3_kernel<<<cdiv(N, 256), 256>>>(N);
    fill_kernel<<<cdiv(E, 256), 256>>>(E, src, dst);

    // h = relu(x @ W_in + b_in)
    pers_gemm<<<GRID_PERS, 256, PERS1_SMEM>>>(N, x, p_B, b_in, p_h, 1);

    for (int l = 0; l < LYR; l++) {
        // A = (l==0) ? h (identity) : pre (inline LN+relu). Fused next adot.
        pers_dual_gemm<<<GRID_PERS, 256, PERS2_SMEM>>>(
            N, invN,
            (l == 0) ? p_h : p_pre, (l == 0) ? 0 : 1,
            p_stats + (l - 1) * 2 * H,
            gamma + (l - 1) * H, beta + (l - 1) * H,
            Wa + l * 2 * H, p_a,
            p_B + (1 + l) * BMAT_WORDS, p_B + (5 + l) * BMAT_WORDS,
            bm + l * H, br + l * H, p_m, p_pre);
        // pre += sum_in sigmoid(...)*m[src]; fused LN stats
        gather_kernel<<<2048, 256>>>(N, p_a, ba + l, p_m, p_pre,
                                     p_stats + l * 2 * H);
    }

    // pool = segment_sum(LN(pre_3)); restores g_deg
    pool_kernel<<<rowBlocks, 256>>>(N, invN, p_pre, p_stats + 3 * 2 * H,
                                    gamma + 3 * H, beta + 3 * H, batch, p_pool);
    // head; restores g_pool/g_stats
    head_kernel<<<1, 256>>>(p_pool, W1, b1, W2, b2, (float*)d_out, p_stats);
}

// round 11
// speedup vs baseline: 1.4650x; 1.4650x over previous
#include <cuda_runtime.h>
#include <cuda_fp16.h>
#include <math.h>
#include <stdint.h>

#define H 128
#define LYR 4
#define G 64
#define C 10
#define MAXN 50048
#define MAXE 600064
#define EPSV 1e-5f

// Persistent device scratch (static, no allocation).
// INVARIANT: g_deg, g_pool, g_stats are zero at entry (zero-initialized .bss;
// restored to zero by pool_kernel / head_kernel at the end of every call).
__device__ __align__(16) float g_h[MAXN * H];
__device__ __align__(16) float g_m[MAXN * H];
__device__ __align__(16) float g_pre[MAXN * H];
__device__ __align__(16) float g_a[MAXN * 2];
__device__ __align__(16) float g_stats[LYR * 2 * H];
__device__ __align__(16) float g_pool[G * H];
__device__ int g_deg[MAXN];
__device__ int g_off[MAXN];
__device__ int g_cursor[MAXN];
__device__ int g_adj[MAXE];          // src node per CSR slot
__device__ int g_btot[32];
// 9 matrices, each: hi half + lo half (unscaled fp16 residual)
#define SROW 136
#define HALF_WORDS (64 * SROW)                // 8704 words (one 128x128 f16 image)
#define BMAT_WORDS (2 * HALF_WORDS)
__device__ __align__(16) uint32_t g_Bsplit[9 * BMAT_WORDS];

static inline int cdiv(int a, int b) { return (a + b - 1) / b; }

// ---------------------------------------------------------------------------
// fp16 helpers
// ---------------------------------------------------------------------------
__device__ __forceinline__ uint32_t pack_h2(float f0, float f1) {
    __half2 h = __floats2half2_rn(f0, f1);
    return *(uint32_t*)&h;
}

__device__ __forceinline__ void mma16816(float* d, const uint32_t* a,
                                         const uint32_t* b) {
    asm volatile(
        "mma.sync.aligned.m16n8k16.row.col.f32.f16.f16.f32 "
        "{%0,%1,%2,%3}, {%4,%5,%6,%7}, {%8,%9}, {%0,%1,%2,%3};\n"
        : "+f"(d[0]), "+f"(d[1]), "+f"(d[2]), "+f"(d[3])
        : "r"(a[0]), "r"(a[1]), "r"(a[2]), "r"(a[3]),
          "r"(b[0]), "r"(b[1]));
}

// ---------------------------------------------------------------------------
// Prep: split weight matrices (B = W^T) into fp16 hi + unscaled-lo images.
// Image layout: word kp*136 + n (kp = k-pair, n = output col).
// ---------------------------------------------------------------------------
__global__ __launch_bounds__(256) void prep_kernel(
    const float* __restrict__ W_in, const float* __restrict__ Wm,
    const float* __restrict__ Wr)
{
    int mat = blockIdx.y;
    const float* W = (mat == 0) ? W_in
                   : (mat < 5) ? Wm + (mat - 1) * H * H
                               : Wr + (mat - 5) * H * H;
    uint32_t* out = g_Bsplit + mat * BMAT_WORDS;
    int p = blockIdx.x * 256 + threadIdx.x;
    int n = p >> 6;
    int kp = p & 63;
    int k = kp * 2;
    float f0 = W[k * H + n];
    float f1 = W[(k + 1) * H + n];
    __half h0 = __float2half_rn(f0);
    __half h1 = __float2half_rn(f1);
    float r0 = f0 - __half2float(h0);
    float r1 = f1 - __half2float(h1);
    out[kp * SROW + n] = pack_h2(__half2float(h0), __half2float(h1));
    out[HALF_WORDS + kp * SROW + n] = pack_h2(r0, r1);
}

// ---------------------------------------------------------------------------
// GEMM building blocks (fp16, A single image, B hi+lo, ONE accumulator)
// ---------------------------------------------------------------------------
#define PERS1_SMEM (3 * HALF_WORDS * 4)       // 104448 B (A + one B pair)
#define PERS2_SMEM (5 * HALF_WORDS * 4)       // 174080 B (A + two B pairs)
#define GRID_PERS 148

__device__ __forceinline__ void gemm_copyB(uint32_t* dstB, const uint32_t* Bimg,
                                           int tid) {
    uint4* bs = (uint4*)dstB;
    const uint4* bg = (const uint4*)Bimg;
#pragma unroll
    for (int i = 0; i < 17; i++)
        bs[tid + i * 256] = bg[tid + i * 256];
}

// Convert A tile (raw fp32, optional affine LN + relu) to fp16 image;
// fused adot partials.
__device__ __forceinline__ void gemm_cvtA(uint32_t* Ah, const float* Araw,
    int M, int rowBase, int tid,
    const float* s_scale, const float* s_shift,
    const float* s_ws, const float* s_wd,
    float (*s_pdS)[128], float (*s_pdD)[128])
{
    int row = tid & 127;
    int khalf = tid >> 7;
    bool ok = (rowBase + row) < M;
    const float4* Ar = (const float4*)(Araw + (size_t)(rowBase + row) * 128 + khalf * 64);
    float ss = 0.f, sd = 0.f;
#pragma unroll
    for (int i = 0; i < 16; i++) {
        float4 p = ok ? Ar[i] : make_float4(0.f, 0.f, 0.f, 0.f);
        int k = khalf * 64 + i * 4;
        float4 v;
        v.x = fmaxf(p.x * s_scale[k + 0] + s_shift[k + 0], 0.f);
        v.y = fmaxf(p.y * s_scale[k + 1] + s_shift[k + 1], 0.f);
        v.z = fmaxf(p.z * s_scale[k + 2] + s_shift[k + 2], 0.f);
        v.w = fmaxf(p.w * s_scale[k + 3] + s_shift[k + 3], 0.f);
        if (!ok) { v.x = 0.f; v.y = 0.f; v.z = 0.f; v.w = 0.f; }
        ss += v.x * s_ws[k] + v.y * s_ws[k + 1] + v.z * s_ws[k + 2] + v.w * s_ws[k + 3];
        sd += v.x * s_wd[k] + v.y * s_wd[k + 1] + v.z * s_wd[k + 2] + v.w * s_wd[k + 3];
        int kp = khalf * 32 + i * 2;
        Ah[kp * SROW + row]       = pack_h2(v.x, v.y);
        Ah[(kp + 1) * SROW + row] = pack_h2(v.z, v.w);
    }
    s_pdS[khalf][row] = ss;
    s_pdD[khalf][row] = sd;
}

// Plain convert (no LN, no adot) for the input GEMM
__device__ __forceinline__ void gemm_cvtA_plain(uint32_t* Ah, const float* Araw,
                                                int M, int rowBase, int tid)
{
    int row = tid & 127;
    int khalf = tid >> 7;
    bool ok = (rowBase + row) < M;
    const float4* Ar = (const float4*)(Araw + (size_t)(rowBase + row) * 128 + khalf * 64);
#pragma unroll
    for (int i = 0; i < 16; i++) {
        float4 v = ok ? Ar[i] : make_float4(0.f, 0.f, 0.f, 0.f);
        int kp = khalf * 32 + i * 2;
        Ah[kp * SROW + row]       = pack_h2(v.x, v.y);
        Ah[(kp + 1) * SROW + row] = pack_h2(v.z, v.w);
    }
}

// Single-accumulator compute: acc += A*B_hi + A*B_lo
__device__ __forceinline__ void gemm_compute(const uint32_t* Ah,
    const uint32_t* Bb, int warp_m, int warp_n, int g, int tg,
    float acc[2][8][4])
{
#pragma unroll
    for (int mi = 0; mi < 2; mi++)
#pragma unroll
        for (int ni = 0; ni < 8; ni++)
#pragma unroll
            for (int q = 0; q < 4; q++) acc[mi][ni][q] = 0.f;

#pragma unroll
    for (int s = 0; s < 8; s++) {
        int q0 = s * 8 + tg;
        int q1 = s * 8 + 4 + tg;
        uint32_t a[2][4];
#pragma unroll
        for (int mi = 0; mi < 2; mi++) {
            int r0 = warp_m + mi * 16 + g;
            a[mi][0] = Ah[q0 * SROW + r0];
            a[mi][1] = Ah[q0 * SROW + r0 + 8];
            a[mi][2] = Ah[q1 * SROW + r0];
            a[mi][3] = Ah[q1 * SROW + r0 + 8];
        }
#pragma unroll
        for (int ni = 0; ni < 8; ni++) {
            int cn = warp_n + ni * 8 + g;
            uint32_t bhi[2], blo[2];
            bhi[0] = Bb[q0 * SROW + cn];
            bhi[1] = Bb[q1 * SROW + cn];
            blo[0] = Bb[HALF_WORDS + q0 * SROW + cn];
            blo[1] = Bb[HALF_WORDS + q1 * SROW + cn];
#pragma unroll
            for (int mi = 0; mi < 2; mi++) {
                mma16816(acc[mi][ni], a[mi], bhi);
                mma16816(acc[mi][ni], a[mi], blo);
            }
        }
    }
}

__device__ __forceinline__ void gemm_store(float acc[2][8][4],
    const float* __restrict__ bias, float* __restrict__ Cm,
    int M, int rowBase, int warp_m, int warp_n, int g, int tg, int relu)
{
    float bv[8][2];
#pragma unroll
    for (int ni = 0; ni < 8; ni++) {
        int cb = warp_n + ni * 8 + 2 * tg;
        bv[ni][0] = bias[cb];
        bv[ni][1] = bias[cb + 1];
    }
#pragma unroll
    for (int mi = 0; mi < 2; mi++) {
#pragma unroll
        for (int rh = 0; rh < 2; rh++) {
            int row = rowBase + warp_m + mi * 16 + g + rh * 8;
            if (row < M) {
#pragma unroll
                for (int ni = 0; ni < 8; ni++) {
                    float vx = acc[mi][ni][rh * 2 + 0] + bv[ni][0];
                    float vy = acc[mi][ni][rh * 2 + 1] + bv[ni][1];
                    if (relu) { vx = fmaxf(vx, 0.f); vy = fmaxf(vy, 0.f); }
                    float2 o; o.x = vx; o.y = vy;
                    *(float2*)(Cm + (size_t)row * 128 + warp_n + ni * 8 + 2 * tg) = o;
                }
            }
        }
    }
}

// Persistent single GEMM (input layer): C = relu(A @ W + b). B copied once.
__global__ __launch_bounds__(256) void pers_gemm(
    int M, const float* __restrict__ A, const uint32_t* __restrict__ Bimg,
    const float* __restrict__ bias, float* __restrict__ Cm, int relu)
{
    extern __shared__ uint32_t sm[];
    uint32_t* Ah = sm;
    uint32_t* Bb = sm + HALF_WORDS;

    int tid = threadIdx.x;
    int warp = tid >> 5, lane = tid & 31;
    int g = lane >> 2, tg = lane & 3;
    int warp_m = (warp >> 1) * 32;
    int warp_n = (warp & 1) * 64;
    int ntiles = (M + 127) >> 7;

    gemm_copyB(Bb, Bimg, tid);

    for (int tile = blockIdx.x; tile < ntiles; tile += gridDim.x) {
        __syncthreads();
        gemm_cvtA_plain(Ah, A, M, tile * 128, tid);
        __syncthreads();
        float acc[2][8][4];
        gemm_compute(Ah, Bb, warp_m, warp_n, g, tg, acc);
        gemm_store(acc, bias, Cm, M, tile * 128, warp_m, warp_n, g, tg, relu);
    }
}

// ---------------------------------------------------------------------------
// Persistent dual GEMM with fused input-normalization and adot.
// A_eff[r][c] = relu(Araw[r][c] * scale[c] + shift[c])  (affine LN or identity)
// Outputs: m = A_eff@Wm + bm ; pre = A_eff@Wr + br ; a[r] = A_eff[r]·(ws|wd).
// In-place Araw == pre output is safe (tile ownership is exclusive).
// ---------------------------------------------------------------------------
__global__ __launch_bounds__(256) void pers_dual_gemm(
    int M, float invN, const float* __restrict__ Araw, int useLN,
    const float* __restrict__ stats,
    const float* __restrict__ gamma, const float* __restrict__ beta,
    const float* __restrict__ Wa_l, float* __restrict__ a_out,
    const uint32_t* __restrict__ Bm_img, const uint32_t* __restrict__ Br_img,
    const float* __restrict__ bm, const float* __restrict__ br,
    float* __restrict__ Cm, float* __restrict__ Cpre)
{
    extern __shared__ uint32_t sm[];
    uint32_t* Ah  = sm;
    uint32_t* Bmb = sm + HALF_WORDS;
    uint32_t* Brb = sm + 3 * HALF_WORDS;
    __shared__ float s_scale[128], s_shift[128];
    __shared__ float s_ws[128], s_wd[128];
    __shared__ float s_pdS[2][128], s_pdD[2][128];

    int tid = threadIdx.x;
    int warp = tid >> 5, lane = tid & 31;
    int g = lane >> 2, tg = lane & 3;
    int warp_m = (warp >> 1) * 32;
    int warp_n = (warp & 1) * 64;
    int ntiles = (M + 127) >> 7;

    if (tid < 128) {
        float sc = 1.f, sh = 0.f;
        if (useLN) {
            float s = stats[tid], q = stats[128 + tid];
            float mu = s * invN;
            float var = q * invN - mu * mu;
            float rs = rsqrtf(var + EPSV);
            sc = rs * gamma[tid];
            sh = beta[tid] - mu * sc;
        }
        s_scale[tid] = sc;
        s_shift[tid] = sh;
        s_ws[tid] = Wa_l[tid];
        s_wd[tid] = Wa_l[128 + tid];
    }
    gemm_copyB(Bmb, Bm_img, tid);
    gemm_copyB(Brb, Br_img, tid);

    for (int tile = blockIdx.x; tile < ntiles; tile += gridDim.x) {
        int rowBase = tile * 128;
        __syncthreads();   // B/scale ready; prev iter compute + a_out done
        gemm_cvtA(Ah, Araw, M, rowBase, tid, s_scale, s_shift, s_ws, s_wd,
                  s_pdS, s_pdD);
        __syncthreads();
        if (tid < 128 && rowBase + tid < M) {
            a_out[2 * (rowBase + tid)]     = s_pdS[0][tid] + s_pdS[1][tid];
            a_out[2 * (rowBase + tid) + 1] = s_pdD[0][tid] + s_pdD[1][tid];
        }
        {
            float acc[2][8][4];
            gemm_compute(Ah, Bmb, warp_m, warp_n, g, tg, acc);
            gemm_store(acc, bm, Cm, M, rowBase, warp_m, warp_n, g, tg, 0);
        }
        {
            float acc[2][8][4];
            gemm_compute(Ah, Brb, warp_m, warp_n, g, tg, acc);
            gemm_store(acc, br, Cpre, M, rowBase, warp_m, warp_n, g, tg, 0);
        }
    }
}

// ---------------------------------------------------------------------------
// CSR build: count (g_deg is zero at entry by invariant), scan, fill
// ---------------------------------------------------------------------------
__global__ __launch_bounds__(256) void count_kernel(int E, const int* __restrict__ dst) {
    int i = blockIdx.x * 256 + threadIdx.x;
    if (i < E) atomicAdd(&g_deg[dst[i]], 1);
}

#define SCB 4096   // elements per scan block (256 thr x 16)

__global__ __launch_bounds__(256) void scan1_kernel(int N) {
    __shared__ int wsum[8];
    int tid = threadIdx.x;
    int lane = tid & 31, w = tid >> 5;
    int base = blockIdx.x * SCB + tid * 16;
    int v[16];
    int s = 0;
#pragma unroll
    for (int i = 0; i < 16; i++) {
        int idx = base + i;
        v[i] = (idx < N) ? g_deg[idx] : 0;
        s += v[i];
    }
    int incl = s;
#pragma unroll
    for (int d = 1; d < 32; d <<= 1) {
        int t = __shfl_up_sync(0xFFFFFFFFu, incl, d);
        if (lane >= d) incl += t;
    }
    if (lane == 31) wsum[w] = incl;
    __syncthreads();
    if (tid == 0) {
        int c = 0;
#pragma unroll
        for (int i = 0; i < 8; i++) { int x = wsum[i]; wsum[i] = c; c += x; }
        g_btot[blockIdx.x] = c;
    }
    __syncthreads();
    int run = incl - s + wsum[w];
#pragma unroll
    for (int i = 0; i < 16; i++) {
        int idx = base + i;
        if (idx < N) g_off[idx] = run;
        run += v[i];
    }
}

// scan3: adds inline prefix of block totals (nb <= 13)
__global__ __launch_bounds__(256) void scan3_kernel(int N) {
    int i = blockIdx.x * 256 + threadIdx.x;
    if (i < N) {
        int b = i / SCB;
        int add = 0;
        for (int j = 0; j < b; j++) add += g_btot[j];
        int o = g_off[i] + add;
        g_off[i] = o;
        g_cursor[i] = o;
    }
}

__global__ __launch_bounds__(256) void fill_kernel(
    int E, const int* __restrict__ src, const int* __restrict__ dst)
{
    int i = blockIdx.x * 256 + threadIdx.x;
    if (i < E) {
        int slot = atomicAdd(&g_cursor[dst[i]], 1);
        g_adj[slot] = src[i];
    }
}

// ---------------------------------------------------------------------------
// Gather: pre[d] += sum_in sigmoid(a_src[s]+a_dst[d]+ba)*m[s]
// CSR, warp per row, 1-deep prefetch of (m row, a_src). Fused LN stats.
// ---------------------------------------------------------------------------
__global__ __launch_bounds__(256) void gather_kernel(
    int N, const float* __restrict__ a, const float* __restrict__ ba_l,
    const float* __restrict__ m, float* __restrict__ pre,
    float* __restrict__ stats)
{
    __shared__ float redS[8][128], redQ[8][128];
    int tid = threadIdx.x;
    int w = tid >> 5, lane = tid & 31;
    float bav = ba_l[0];
    float4 s1 = make_float4(0.f, 0.f, 0.f, 0.f);
    float4 s2 = make_float4(0.f, 0.f, 0.f, 0.f);
    const float4* m4 = (const float4*)m;

    for (int row = blockIdx.x * 8 + w; row < N; row += gridDim.x * 8) {
        float4 v = ((const float4*)pre)[row * 32 + lane];
        float ad = a[2 * row + 1] + bav;
        int off = g_off[row];
        int deg = g_deg[row];
        const int* ep = g_adj + off;
        if (deg > 0) {
            int s0 = ep[0];
            float4 mv_n = m4[(size_t)s0 * 32 + lane];
            float z_n = a[2 * s0];
            for (int e = 0; e < deg; e++) {
                float4 mv = mv_n;
                float z = z_n + ad;
                if (e + 1 < deg) {
                    int sn = ep[e + 1];
                    mv_n = m4[(size_t)sn * 32 + lane];
                    z_n = a[2 * sn];
                }
                float gate = 1.f / (1.f + __expf(-z));
                v.x += gate * mv.x; v.y += gate * mv.y;
                v.z += gate * mv.z; v.w += gate * mv.w;
            }
        }
        ((float4*)pre)[row * 32 + lane] = v;
        s1.x += v.x; s1.y += v.y; s1.z += v.z; s1.w += v.w;
        s2.x += v.x * v.x; s2.y += v.y * v.y;
        s2.z += v.z * v.z; s2.w += v.w * v.w;
    }
    *(float4*)&redS[w][lane * 4] = s1;
    *(float4*)&redQ[w][lane * 4] = s2;
    __syncthreads();
    if (tid < 128) {
        float aa = 0.f, bb = 0.f;
#pragma unroll
        for (int i = 0; i < 8; i++) { aa += redS[i][tid]; bb += redQ[i][tid]; }
        atomicAdd(&stats[tid], aa);
        atomicAdd(&stats[128 + tid], bb);
    }
}

// ---------------------------------------------------------------------------
// Final pool: normalize pre (layer 3) on the fly and pool. Warp per row.
// Also restores g_deg = 0 (state invariant for the next call).
// ---------------------------------------------------------------------------
__global__ __launch_bounds__(256) void pool_kernel(
    int N, float invN, const float* __restrict__ pre,
    const float* __restrict__ stats,
    const float* __restrict__ gamma, const float* __restrict__ beta,
    const int* __restrict__ batch, float* __restrict__ pool)
{
    int tid = threadIdx.x;
    int w = tid >> 5, lane = tid & 31;
    float sc[4], sh[4];
#pragma unroll
    for (int i = 0; i < 4; i++) {
        int c = lane * 4 + i;
        float s = stats[c], q = stats[128 + c];
        float mu = s * invN;
        float var = q * invN - mu * mu;
        float rs = rsqrtf(var + EPSV);
        sc[i] = rs * gamma[c];
        sh[i] = beta[c] - mu * sc[i];
    }
    for (int row = blockIdx.x * 8 + w; row < N; row += gridDim.x * 8) {
        float4 p = ((const float4*)pre)[row * 32 + lane];
        float4 v;
        v.x = fmaxf(p.x * sc[0] + sh[0], 0.f);
        v.y = fmaxf(p.y * sc[1] + sh[1], 0.f);
        v.z = fmaxf(p.z * sc[2] + sh[2], 0.f);
        v.w = fmaxf(p.w * sc[3] + sh[3], 0.f);
        int b = batch[row];
        atomicAdd(((float4*)(pool + (size_t)b * 128)) + lane, v);
        if (lane == 0) g_deg[row] = 0;     // restore invariant
    }
}

// ---------------------------------------------------------------------------
// MLP head; restores g_pool and g_stats to zero (state invariant).
// ---------------------------------------------------------------------------
__global__ __launch_bounds__(256) void head_kernel(
    float* __restrict__ pool,
    const float* __restrict__ W1, const float* __restrict__ b1,
    const float* __restrict__ W2, const float* __restrict__ b2,
    float* __restrict__ out, float* __restrict__ stats)
{
    __shared__ float sh[G * 64];
    int tid = threadIdx.x;
    for (int o = tid; o < G * 64; o += 256) {
        int g = o >> 6, j = o & 63;
        float s = b1[j];
        const float* pr = pool + g * 128;
#pragma unroll 4
        for (int k = 0; k < 128; k++) s += pr[k] * W1[k * 64 + j];
        sh[o] = fmaxf(s, 0.f);
    }
    __syncthreads();            // all reads of pool complete
    for (int o = tid; o < G * H; o += 256) pool[o] = 0.f;
    for (int o = tid; o < LYR * 2 * H; o += 256) stats[o] = 0.f;
    for (int o = tid; o < G * C; o += 256) {
        int g = o / C, c = o % C;
        float s = b2[c];
        const float* hr = sh + g * 64;
#pragma unroll 4
        for (int k = 0; k < 64; k++) s += hr[k] * W2[k * C + c];
        out[o] = s * 0.5f;   // /TEMP
    }
}

// ---------------------------------------------------------------------------
// Launch
// ---------------------------------------------------------------------------
extern "C" void kernel_launch(void* const* d_in, const int* in_sizes, int n_in,
                              void* d_out, int out_size)
{
    const float* x     = (const float*)d_in[0];
    const int*   ei    = (const int*)d_in[1];
    const int*   batch = (const int*)d_in[2];
    const float* W_in  = (const float*)d_in[3];
    const float* b_in  = (const float*)d_in[4];
    const float* Wa    = (const float*)d_in[5];
    const float* ba    = (const float*)d_in[6];
    const float* Wm    = (const float*)d_in[7];
    const float* bm    = (const float*)d_in[8];
    const float* Wr    = (const float*)d_in[9];
    const float* br    = (const float*)d_in[10];
    const float* gamma = (const float*)d_in[11];
    const float* beta  = (const float*)d_in[12];
    const float* W1    = (const float*)d_in[13];
    const float* b1    = (const float*)d_in[14];
    const float* W2    = (const float*)d_in[15];
    const float* b2    = (const float*)d_in[16];

    int N = in_sizes[0] / 128;
    int E = in_sizes[1] / 2;
    const int* src = ei;
    const int* dst = ei + E;

    cudaFuncSetAttribute(pers_gemm, cudaFuncAttributeMaxDynamicSharedMemorySize,
                         PERS1_SMEM);
    cudaFuncSetAttribute(pers_dual_gemm, cudaFuncAttributeMaxDynamicSharedMemorySize,
                         PERS2_SMEM);

    float *p_h, *p_m, *p_pre, *p_a, *p_pool, *p_stats;
    uint32_t* p_B;
    cudaGetSymbolAddress((void**)&p_h, g_h);
    cudaGetSymbolAddress((void**)&p_m, g_m);
    cudaGetSymbolAddress((void**)&p_pre, g_pre);
    cudaGetSymbolAddress((void**)&p_a, g_a);
    cudaGetSymbolAddress((void**)&p_pool, g_pool);
    cudaGetSymbolAddress((void**)&p_stats, g_stats);
    cudaGetSymbolAddress((void**)&p_B, g_Bsplit);

    int rowBlocks = cdiv(N, 8);
    int scanBlocks = cdiv(N, SCB);
    float invN = 1.0f / (float)N;

    // --- one-time per call: weights prep + CSR build (g_deg zero by invariant)
    prep_kernel<<<dim3(32, 9), 256>>>(W_in, Wm, Wr);
    count_kernel<<<cdiv(E, 256), 256>>>(E, dst);
    scan1_kernel<<<scanBlocks, 256>>>(N);
    scan3_kernel<<<cdiv(N, 256), 256>>>(N);
    fill_kernel<<<cdiv(E, 256), 256>>>(E, src, dst);

    // h = relu(x @ W_in + b_in)
    pers_gemm<<<GRID_PERS, 256, PERS1_SMEM>>>(N, x, p_B, b_in, p_h, 1);

    for (int l = 0; l < LYR; l++) {
        // A = (l==0) ? h (identity) : pre (inline LN+relu). Fused next adot.
        pers_dual_gemm<<<GRID_PERS, 256, PERS2_SMEM>>>(
            N, invN,
            (l == 0) ? p_h : p_pre, (l == 0) ? 0 : 1,
            p_stats + (l - 1) * 2 * H,
            gamma + (l - 1) * H, beta + (l - 1) * H,
            Wa + l * 2 * H, p_a,
            p_B + (1 + l) * BMAT_WORDS, p_B + (5 + l) * BMAT_WORDS,
            bm + l * H, br + l * H, p_m, p_pre);
        // pre += sum_in sigmoid(...)*m[src]; fused LN stats
        gather_kernel<<<2048, 256>>>(N, p_a, ba + l, p_m, p_pre,
                                     p_stats + l * 2 * H);
    }

    // pool = segment_sum(LN(pre_3)); restores g_deg
    pool_kernel<<<rowBlocks, 256>>>(N, invN, p_pre, p_stats + 3 * 2 * H,
                                    gamma + 3 * H, beta + 3 * H, batch, p_pool);
    // head; restores g_pool/g_stats
    head_kernel<<<1, 256>>>(p_pool, W1, b1, W2, b2, (float*)d_out, p_stats);
}

// round 12
// speedup vs baseline: 1.4799x; 1.0102x over previous
#include <cuda_runtime.h>
#include <cuda_fp16.h>
#include <math.h>
#include <stdint.h>

#define H 128
#define LYR 4
#define G 64
#define C 10
#define MAXN 50048
#define MAXE 600064
#define EPSV 1e-5f

// Persistent device scratch (static, no allocation).
// INVARIANT: g_deg, g_pool, g_stats are zero at entry (zero-initialized .bss;
// restored to zero by pool_kernel / head_kernel at the end of every call).
__device__ __align__(16) float g_h[MAXN * H];
__device__ __align__(16) uint32_t g_m16[MAXN * 64];   // m in half2, 64 words/row
__device__ __align__(16) float g_pre[MAXN * H];
__device__ __align__(16) float g_a[MAXN * 2];
__device__ __align__(16) float g_stats[LYR * 2 * H];
__device__ __align__(16) float g_pool[G * H];
__device__ int g_deg[MAXN];
__device__ int g_off[MAXN];
__device__ int g_cursor[MAXN];
__device__ int g_adj[MAXE];          // src node per CSR slot
__device__ int g_btot[32];
// 9 matrices, each: hi half + lo half (unscaled fp16 residual)
#define SROW 136
#define HALF_WORDS (64 * SROW)                // 8704 words (one 128x128 f16 image)
#define BMAT_WORDS (2 * HALF_WORDS)
__device__ __align__(16) uint32_t g_Bsplit[9 * BMAT_WORDS];

static inline int cdiv(int a, int b) { return (a + b - 1) / b; }

// ---------------------------------------------------------------------------
// fp16 helpers
// ---------------------------------------------------------------------------
__device__ __forceinline__ uint32_t pack_h2(float f0, float f1) {
    __half2 h = __floats2half2_rn(f0, f1);
    return *(uint32_t*)&h;
}

__device__ __forceinline__ void mma16816(float* d, const uint32_t* a,
                                         const uint32_t* b) {
    asm volatile(
        "mma.sync.aligned.m16n8k16.row.col.f32.f16.f16.f32 "
        "{%0,%1,%2,%3}, {%4,%5,%6,%7}, {%8,%9}, {%0,%1,%2,%3};\n"
        : "+f"(d[0]), "+f"(d[1]), "+f"(d[2]), "+f"(d[3])
        : "r"(a[0]), "r"(a[1]), "r"(a[2]), "r"(a[3]),
          "r"(b[0]), "r"(b[1]));
}

// ---------------------------------------------------------------------------
// Prep: split weight matrices (B = W^T) into fp16 hi + unscaled-lo images.
// ---------------------------------------------------------------------------
__global__ __launch_bounds__(256) void prep_kernel(
    const float* __restrict__ W_in, const float* __restrict__ Wm,
    const float* __restrict__ Wr)
{
    int mat = blockIdx.y;
    const float* W = (mat == 0) ? W_in
                   : (mat < 5) ? Wm + (mat - 1) * H * H
                               : Wr + (mat - 5) * H * H;
    uint32_t* out = g_Bsplit + mat * BMAT_WORDS;
    int p = blockIdx.x * 256 + threadIdx.x;
    int n = p >> 6;
    int kp = p & 63;
    int k = kp * 2;
    float f0 = W[k * H + n];
    float f1 = W[(k + 1) * H + n];
    __half h0 = __float2half_rn(f0);
    __half h1 = __float2half_rn(f1);
    float r0 = f0 - __half2float(h0);
    float r1 = f1 - __half2float(h1);
    out[kp * SROW + n] = pack_h2(__half2float(h0), __half2float(h1));
    out[HALF_WORDS + kp * SROW + n] = pack_h2(r0, r1);
}

// ---------------------------------------------------------------------------
// GEMM building blocks (fp16, A single image, B hi+lo, ONE accumulator)
// ---------------------------------------------------------------------------
#define PERS1_SMEM (3 * HALF_WORDS * 4)       // 104448 B (A + one B pair)
#define PERS2_SMEM (5 * HALF_WORDS * 4)       // 174080 B (A + two B pairs)
#define GRID_PERS 148

__device__ __forceinline__ void gemm_copyB(uint32_t* dstB, const uint32_t* Bimg,
                                           int tid) {
    uint4* bs = (uint4*)dstB;
    const uint4* bg = (const uint4*)Bimg;
#pragma unroll
    for (int i = 0; i < 17; i++)
        bs[tid + i * 256] = bg[tid + i * 256];
}

// Convert A tile (raw fp32, optional affine LN + relu) to fp16 image;
// fused adot partials.
__device__ __forceinline__ void gemm_cvtA(uint32_t* Ah, const float* Araw,
    int M, int rowBase, int tid,
    const float* s_scale, const float* s_shift,
    const float* s_ws, const float* s_wd,
    float (*s_pdS)[128], float (*s_pdD)[128])
{
    int row = tid & 127;
    int khalf = tid >> 7;
    bool ok = (rowBase + row) < M;
    const float4* Ar = (const float4*)(Araw + (size_t)(rowBase + row) * 128 + khalf * 64);
    float ss = 0.f, sd = 0.f;
#pragma unroll
    for (int i = 0; i < 16; i++) {
        float4 p = ok ? Ar[i] : make_float4(0.f, 0.f, 0.f, 0.f);
        int k = khalf * 64 + i * 4;
        float4 v;
        v.x = fmaxf(p.x * s_scale[k + 0] + s_shift[k + 0], 0.f);
        v.y = fmaxf(p.y * s_scale[k + 1] + s_shift[k + 1], 0.f);
        v.z = fmaxf(p.z * s_scale[k + 2] + s_shift[k + 2], 0.f);
        v.w = fmaxf(p.w * s_scale[k + 3] + s_shift[k + 3], 0.f);
        if (!ok) { v.x = 0.f; v.y = 0.f; v.z = 0.f; v.w = 0.f; }
        ss += v.x * s_ws[k] + v.y * s_ws[k + 1] + v.z * s_ws[k + 2] + v.w * s_ws[k + 3];
        sd += v.x * s_wd[k] + v.y * s_wd[k + 1] + v.z * s_wd[k + 2] + v.w * s_wd[k + 3];
        int kp = khalf * 32 + i * 2;
        Ah[kp * SROW + row]       = pack_h2(v.x, v.y);
        Ah[(kp + 1) * SROW + row] = pack_h2(v.z, v.w);
    }
    s_pdS[khalf][row] = ss;
    s_pdD[khalf][row] = sd;
}

// Plain convert (no LN, no adot) for the input GEMM
__device__ __forceinline__ void gemm_cvtA_plain(uint32_t* Ah, const float* Araw,
                                                int M, int rowBase, int tid)
{
    int row = tid & 127;
    int khalf = tid >> 7;
    bool ok = (rowBase + row) < M;
    const float4* Ar = (const float4*)(Araw + (size_t)(rowBase + row) * 128 + khalf * 64);
#pragma unroll
    for (int i = 0; i < 16; i++) {
        float4 v = ok ? Ar[i] : make_float4(0.f, 0.f, 0.f, 0.f);
        int kp = khalf * 32 + i * 2;
        Ah[kp * SROW + row]       = pack_h2(v.x, v.y);
        Ah[(kp + 1) * SROW + row] = pack_h2(v.z, v.w);
    }
}

// Single-accumulator compute: acc += A*B_hi + A*B_lo
__device__ __forceinline__ void gemm_compute(const uint32_t* Ah,
    const uint32_t* Bb, int warp_m, int warp_n, int g, int tg,
    float acc[2][8][4])
{
#pragma unroll
    for (int mi = 0; mi < 2; mi++)
#pragma unroll
        for (int ni = 0; ni < 8; ni++)
#pragma unroll
            for (int q = 0; q < 4; q++) acc[mi][ni][q] = 0.f;

#pragma unroll
    for (int s = 0; s < 8; s++) {
        int q0 = s * 8 + tg;
        int q1 = s * 8 + 4 + tg;
        uint32_t a[2][4];
#pragma unroll
        for (int mi = 0; mi < 2; mi++) {
            int r0 = warp_m + mi * 16 + g;
            a[mi][0] = Ah[q0 * SROW + r0];
            a[mi][1] = Ah[q0 * SROW + r0 + 8];
            a[mi][2] = Ah[q1 * SROW + r0];
            a[mi][3] = Ah[q1 * SROW + r0 + 8];
        }
#pragma unroll
        for (int ni = 0; ni < 8; ni++) {
            int cn = warp_n + ni * 8 + g;
            uint32_t bhi[2], blo[2];
            bhi[0] = Bb[q0 * SROW + cn];
            bhi[1] = Bb[q1 * SROW + cn];
            blo[0] = Bb[HALF_WORDS + q0 * SROW + cn];
            blo[1] = Bb[HALF_WORDS + q1 * SROW + cn];
#pragma unroll
            for (int mi = 0; mi < 2; mi++) {
                mma16816(acc[mi][ni], a[mi], bhi);
                mma16816(acc[mi][ni], a[mi], blo);
            }
        }
    }
}

// fp32 store (pre / h outputs)
__device__ __forceinline__ void gemm_store(float acc[2][8][4],
    const float* __restrict__ bias, float* __restrict__ Cm,
    int M, int rowBase, int warp_m, int warp_n, int g, int tg, int relu)
{
    float bv[8][2];
#pragma unroll
    for (int ni = 0; ni < 8; ni++) {
        int cb = warp_n + ni * 8 + 2 * tg;
        bv[ni][0] = bias[cb];
        bv[ni][1] = bias[cb + 1];
    }
#pragma unroll
    for (int mi = 0; mi < 2; mi++) {
#pragma unroll
        for (int rh = 0; rh < 2; rh++) {
            int row = rowBase + warp_m + mi * 16 + g + rh * 8;
            if (row < M) {
#pragma unroll
                for (int ni = 0; ni < 8; ni++) {
                    float vx = acc[mi][ni][rh * 2 + 0] + bv[ni][0];
                    float vy = acc[mi][ni][rh * 2 + 1] + bv[ni][1];
                    if (relu) { vx = fmaxf(vx, 0.f); vy = fmaxf(vy, 0.f); }
                    float2 o; o.x = vx; o.y = vy;
                    *(float2*)(Cm + (size_t)row * 128 + warp_n + ni * 8 + 2 * tg) = o;
                }
            }
        }
    }
}

// fp16 store (m output): pack two adjacent cols into one half2 word
__device__ __forceinline__ void gemm_store_m16(float acc[2][8][4],
    const float* __restrict__ bias, uint32_t* __restrict__ Cm16,
    int M, int rowBase, int warp_m, int warp_n, int g, int tg)
{
    float bv[8][2];
#pragma unroll
    for (int ni = 0; ni < 8; ni++) {
        int cb = warp_n + ni * 8 + 2 * tg;
        bv[ni][0] = bias[cb];
        bv[ni][1] = bias[cb + 1];
    }
#pragma unroll
    for (int mi = 0; mi < 2; mi++) {
#pragma unroll
        for (int rh = 0; rh < 2; rh++) {
            int row = rowBase + warp_m + mi * 16 + g + rh * 8;
            if (row < M) {
#pragma unroll
                for (int ni = 0; ni < 8; ni++) {
                    float vx = acc[mi][ni][rh * 2 + 0] + bv[ni][0];
                    float vy = acc[mi][ni][rh * 2 + 1] + bv[ni][1];
                    int col = warp_n + ni * 8 + 2 * tg;
                    Cm16[(size_t)row * 64 + (col >> 1)] = pack_h2(vx, vy);
                }
            }
        }
    }
}

// Persistent single GEMM (input layer): C = relu(A @ W + b). B copied once.
__global__ __launch_bounds__(256) void pers_gemm(
    int M, const float* __restrict__ A, const uint32_t* __restrict__ Bimg,
    const float* __restrict__ bias, float* __restrict__ Cm, int relu)
{
    extern __shared__ uint32_t sm[];
    uint32_t* Ah = sm;
    uint32_t* Bb = sm + HALF_WORDS;

    int tid = threadIdx.x;
    int warp = tid >> 5, lane = tid & 31;
    int g = lane >> 2, tg = lane & 3;
    int warp_m = (warp >> 1) * 32;
    int warp_n = (warp & 1) * 64;
    int ntiles = (M + 127) >> 7;

    gemm_copyB(Bb, Bimg, tid);

    for (int tile = blockIdx.x; tile < ntiles; tile += gridDim.x) {
        __syncthreads();
        gemm_cvtA_plain(Ah, A, M, tile * 128, tid);
        __syncthreads();
        float acc[2][8][4];
        gemm_compute(Ah, Bb, warp_m, warp_n, g, tg, acc);
        gemm_store(acc, bias, Cm, M, tile * 128, warp_m, warp_n, g, tg, relu);
    }
}

// ---------------------------------------------------------------------------
// Persistent dual GEMM with fused input-normalization and adot.
// m output in fp16 (half2), pre output fp32.
// ---------------------------------------------------------------------------
__global__ __launch_bounds__(256) void pers_dual_gemm(
    int M, float invN, const float* __restrict__ Araw, int useLN,
    const float* __restrict__ stats,
    const float* __restrict__ gamma, const float* __restrict__ beta,
    const float* __restrict__ Wa_l, float* __restrict__ a_out,
    const uint32_t* __restrict__ Bm_img, const uint32_t* __restrict__ Br_img,
    const float* __restrict__ bm, const float* __restrict__ br,
    uint32_t* __restrict__ Cm16, float* __restrict__ Cpre)
{
    extern __shared__ uint32_t sm[];
    uint32_t* Ah  = sm;
    uint32_t* Bmb = sm + HALF_WORDS;
    uint32_t* Brb = sm + 3 * HALF_WORDS;
    __shared__ float s_scale[128], s_shift[128];
    __shared__ float s_ws[128], s_wd[128];
    __shared__ float s_pdS[2][128], s_pdD[2][128];

    int tid = threadIdx.x;
    int warp = tid >> 5, lane = tid & 31;
    int g = lane >> 2, tg = lane & 3;
    int warp_m = (warp >> 1) * 32;
    int warp_n = (warp & 1) * 64;
    int ntiles = (M + 127) >> 7;

    if (tid < 128) {
        float sc = 1.f, sh = 0.f;
        if (useLN) {
            float s = stats[tid], q = stats[128 + tid];
            float mu = s * invN;
            float var = q * invN - mu * mu;
            float rs = rsqrtf(var + EPSV);
            sc = rs * gamma[tid];
            sh = beta[tid] - mu * sc;
        }
        s_scale[tid] = sc;
        s_shift[tid] = sh;
        s_ws[tid] = Wa_l[tid];
        s_wd[tid] = Wa_l[128 + tid];
    }
    gemm_copyB(Bmb, Bm_img, tid);
    gemm_copyB(Brb, Br_img, tid);

    for (int tile = blockIdx.x; tile < ntiles; tile += gridDim.x) {
        int rowBase = tile * 128;
        __syncthreads();   // B/scale ready; prev iter compute + a_out done
        gemm_cvtA(Ah, Araw, M, rowBase, tid, s_scale, s_shift, s_ws, s_wd,
                  s_pdS, s_pdD);
        __syncthreads();
        if (tid < 128 && rowBase + tid < M) {
            a_out[2 * (rowBase + tid)]     = s_pdS[0][tid] + s_pdS[1][tid];
            a_out[2 * (rowBase + tid) + 1] = s_pdD[0][tid] + s_pdD[1][tid];
        }
        {
            float acc[2][8][4];
            gemm_compute(Ah, Bmb, warp_m, warp_n, g, tg, acc);
            gemm_store_m16(acc, bm, Cm16, M, rowBase, warp_m, warp_n, g, tg);
        }
        {
            float acc[2][8][4];
            gemm_compute(Ah, Brb, warp_m, warp_n, g, tg, acc);
            gemm_store(acc, br, Cpre, M, rowBase, warp_m, warp_n, g, tg, 0);
        }
    }
}

// ---------------------------------------------------------------------------
// CSR build: count (g_deg is zero at entry by invariant), scan, fill
// ---------------------------------------------------------------------------
__global__ __launch_bounds__(256) void count_kernel(int E, const int* __restrict__ dst) {
    int i = blockIdx.x * 256 + threadIdx.x;
    if (i < E) atomicAdd(&g_deg[dst[i]], 1);
}

#define SCB 4096   // elements per scan block (256 thr x 16)

__global__ __launch_bounds__(256) void scan1_kernel(int N) {
    __shared__ int wsum[8];
    int tid = threadIdx.x;
    int lane = tid & 31, w = tid >> 5;
    int base = blockIdx.x * SCB + tid * 16;
    int v[16];
    int s = 0;
#pragma unroll
    for (int i = 0; i < 16; i++) {
        int idx = base + i;
        v[i] = (idx < N) ? g_deg[idx] : 0;
        s += v[i];
    }
    int incl = s;
#pragma unroll
    for (int d = 1; d < 32; d <<= 1) {
        int t = __shfl_up_sync(0xFFFFFFFFu, incl, d);
        if (lane >= d) incl += t;
    }
    if (lane == 31) wsum[w] = incl;
    __syncthreads();
    if (tid == 0) {
        int c = 0;
#pragma unroll
        for (int i = 0; i < 8; i++) { int x = wsum[i]; wsum[i] = c; c += x; }
        g_btot[blockIdx.x] = c;
    }
    __syncthreads();
    int run = incl - s + wsum[w];
#pragma unroll
    for (int i = 0; i < 16; i++) {
        int idx = base + i;
        if (idx < N) g_off[idx] = run;
        run += v[i];
    }
}

// scan3: adds inline prefix of block totals (nb <= 13)
__global__ __launch_bounds__(256) void scan3_kernel(int N) {
    int i = blockIdx.x * 256 + threadIdx.x;
    if (i < N) {
        int b = i / SCB;
        int add = 0;
        for (int j = 0; j < b; j++) add += g_btot[j];
        int o = g_off[i] + add;
        g_off[i] = o;
        g_cursor[i] = o;
    }
}

__global__ __launch_bounds__(256) void fill_kernel(
    int E, const int* __restrict__ src, const int* __restrict__ dst)
{
    int i = blockIdx.x * 256 + threadIdx.x;
    if (i < E) {
        int slot = atomicAdd(&g_cursor[dst[i]], 1);
        g_adj[slot] = src[i];
    }
}

// ---------------------------------------------------------------------------
// Gather: pre[d] += sum_in sigmoid(a_src[s]+a_dst[d]+ba)*m[s]
// CSR, warp per row, 1-deep prefetch, m in fp16 (8B/lane). Fused LN stats.
// ---------------------------------------------------------------------------
__global__ __launch_bounds__(256) void gather_kernel(
    int N, const float* __restrict__ a, const float* __restrict__ ba_l,
    const uint32_t* __restrict__ m16, float* __restrict__ pre,
    float* __restrict__ stats)
{
    __shared__ float redS[8][128], redQ[8][128];
    int tid = threadIdx.x;
    int w = tid >> 5, lane = tid & 31;
    float bav = ba_l[0];
    float4 s1 = make_float4(0.f, 0.f, 0.f, 0.f);
    float4 s2 = make_float4(0.f, 0.f, 0.f, 0.f);
    const uint2* m2 = (const uint2*)m16;   // 32 uint2 per row

    for (int row = blockIdx.x * 8 + w; row < N; row += gridDim.x * 8) {
        float4 v = ((const float4*)pre)[row * 32 + lane];
        float ad = a[2 * row + 1] + bav;
        int off = g_off[row];
        int deg = g_deg[row];
        const int* ep = g_adj + off;
        if (deg > 0) {
            int s0 = ep[0];
            uint2 mw_n = m2[(size_t)s0 * 32 + lane];
            float z_n = a[2 * s0];
            for (int e = 0; e < deg; e++) {
                uint2 mw = mw_n;
                float z = z_n + ad;
                if (e + 1 < deg) {
                    int sn = ep[e + 1];
                    mw_n = m2[(size_t)sn * 32 + lane];
                    z_n = a[2 * sn];
                }
                float gate = 1.f / (1.f + __expf(-z));
                float2 lo = __half22float2(*(const __half2*)&mw.x);
                float2 hi = __half22float2(*(const __half2*)&mw.y);
                v.x += gate * lo.x; v.y += gate * lo.y;
                v.z += gate * hi.x; v.w += gate * hi.y;
            }
        }
        ((float4*)pre)[row * 32 + lane] = v;
        s1.x += v.x; s1.y += v.y; s1.z += v.z; s1.w += v.w;
        s2.x += v.x * v.x; s2.y += v.y * v.y;
        s2.z += v.z * v.z; s2.w += v.w * v.w;
    }
    *(float4*)&redS[w][lane * 4] = s1;
    *(float4*)&redQ[w][lane * 4] = s2;
    __syncthreads();
    if (tid < 128) {
        float aa = 0.f, bb = 0.f;
#pragma unroll
        for (int i = 0; i < 8; i++) { aa += redS[i][tid]; bb += redQ[i][tid]; }
        atomicAdd(&stats[tid], aa);
        atomicAdd(&stats[128 + tid], bb);
    }
}

// ---------------------------------------------------------------------------
// Final pool: normalize pre (layer 3) on the fly and pool. Warp per row.
// Also restores g_deg = 0 (state invariant for the next call).
// ---------------------------------------------------------------------------
__global__ __launch_bounds__(256) void pool_kernel(
    int N, float invN, const float* __restrict__ pre,
    const float* __restrict__ stats,
    const float* __restrict__ gamma, const float* __restrict__ beta,
    const int* __restrict__ batch, float* __restrict__ pool)
{
    int tid = threadIdx.x;
    int w = tid >> 5, lane = tid & 31;
    float sc[4], sh[4];
#pragma unroll
    for (int i = 0; i < 4; i++) {
        int c = lane * 4 + i;
        float s = stats[c], q = stats[128 + c];
        float mu = s * invN;
        float var = q * invN - mu * mu;
        float rs = rsqrtf(var + EPSV);
        sc[i] = rs * gamma[c];
        sh[i] = beta[c] - mu * sc[i];
    }
    for (int row = blockIdx.x * 8 + w; row < N; row += gridDim.x * 8) {
        float4 p = ((const float4*)pre)[row * 32 + lane];
        float4 v;
        v.x = fmaxf(p.x * sc[0] + sh[0], 0.f);
        v.y = fmaxf(p.y * sc[1] + sh[1], 0.f);
        v.z = fmaxf(p.z * sc[2] + sh[2], 0.f);
        v.w = fmaxf(p.w * sc[3] + sh[3], 0.f);
        int b = batch[row];
        atomicAdd(((float4*)(pool + (size_t)b * 128)) + lane, v);
        if (lane == 0) g_deg[row] = 0;     // restore invariant
    }
}

// ---------------------------------------------------------------------------
// MLP head; restores g_pool and g_stats to zero (state invariant).
// ---------------------------------------------------------------------------
__global__ __launch_bounds__(256) void head_kernel(
    float* __restrict__ pool,
    const float* __restrict__ W1, const float* __restrict__ b1,
    const float* __restrict__ W2, const float* __restrict__ b2,
    float* __restrict__ out, float* __restrict__ stats)
{
    __shared__ float sh[G * 64];
    int tid = threadIdx.x;
    for (int o = tid; o < G * 64; o += 256) {
        int g = o >> 6, j = o & 63;
        float s = b1[j];
        const float* pr = pool + g * 128;
#pragma unroll 4
        for (int k = 0; k < 128; k++) s += pr[k] * W1[k * 64 + j];
        sh[o] = fmaxf(s, 0.f);
    }
    __syncthreads();            // all reads of pool complete
    for (int o = tid; o < G * H; o += 256) pool[o] = 0.f;
    for (int o = tid; o < LYR * 2 * H; o += 256) stats[o] = 0.f;
    for (int o = tid; o < G * C; o += 256) {
        int g = o / C, c = o % C;
        float s = b2[c];
        const float* hr = sh + g * 64;
#pragma unroll 4
        for (int k = 0; k < 64; k++) s += hr[k] * W2[k * C + c];
        out[o] = s * 0.5f;   // /TEMP
    }
}

// ---------------------------------------------------------------------------
// Launch
// ---------------------------------------------------------------------------
extern "C" void kernel_launch(void* const* d_in, const int* in_sizes, int n_in,
                              void* d_out, int out_size)
{
    const float* x     = (const float*)d_in[0];
    const int*   ei    = (const int*)d_in[1];
    const int*   batch = (const int*)d_in[2];
    const float* W_in  = (const float*)d_in[3];
    const float* b_in  = (const float*)d_in[4];
    const float* Wa    = (const float*)d_in[5];
    const float* ba    = (const float*)d_in[6];
    const float* Wm    = (const float*)d_in[7];
    const float* bm    = (const float*)d_in[8];
    const float* Wr    = (const float*)d_in[9];
    const float* br    = (const float*)d_in[10];
    const float* gamma = (const float*)d_in[11];
    const float* beta  = (const float*)d_in[12];
    const float* W1    = (const float*)d_in[13];
    const float* b1    = (const float*)d_in[14];
    const float* W2    = (const float*)d_in[15];
    const float* b2    = (const float*)d_in[16];

    int N = in_sizes[0] / 128;
    int E = in_sizes[1] / 2;
    const int* src = ei;
    const int* dst = ei + E;

    cudaFuncSetAttribute(pers_gemm, cudaFuncAttributeMaxDynamicSharedMemorySize,
                         PERS1_SMEM);
    cudaFuncSetAttribute(pers_dual_gemm, cudaFuncAttributeMaxDynamicSharedMemorySize,
                         PERS2_SMEM);

    float *p_h, *p_pre, *p_a, *p_pool, *p_stats;
    uint32_t *p_m16, *p_B;
    cudaGetSymbolAddress((void**)&p_h, g_h);
    cudaGetSymbolAddress((void**)&p_m16, g_m16);
    cudaGetSymbolAddress((void**)&p_pre, g_pre);
    cudaGetSymbolAddress((void**)&p_a, g_a);
    cudaGetSymbolAddress((void**)&p_pool, g_pool);
    cudaGetSymbolAddress((void**)&p_stats, g_stats);
    cudaGetSymbolAddress((void**)&p_B, g_Bsplit);

    int rowBlocks = cdiv(N, 8);
    int scanBlocks = cdiv(N, SCB);
    float invN = 1.0f / (float)N;

    // --- one-time per call: weights prep + CSR build (g_deg zero by invariant)
    prep_kernel<<<dim3(32, 9), 256>>>(W_in, Wm, Wr);
    count_kernel<<<cdiv(E, 256), 256>>>(E, dst);
    scan1_kernel<<<scanBlocks, 256>>>(N);
    scan3_kernel<<<cdiv(N, 256), 256>>>(N);
    fill_kernel<<<cdiv(E, 256), 256>>>(E, src, dst);

    // h = relu(x @ W_in + b_in)
    pers_gemm<<<GRID_PERS, 256, PERS1_SMEM>>>(N, x, p_B, b_in, p_h, 1);

    for (int l = 0; l < LYR; l++) {
        // A = (l==0) ? h (identity) : pre (inline LN+relu). Fused next adot.
        pers_dual_gemm<<<GRID_PERS, 256, PERS2_SMEM>>>(
            N, invN,
            (l == 0) ? p_h : p_pre, (l == 0) ? 0 : 1,
            p_stats + (l - 1) * 2 * H,
            gamma + (l - 1) * H, beta + (l - 1) * H,
            Wa + l * 2 * H, p_a,
            p_B + (1 + l) * BMAT_WORDS, p_B + (5 + l) * BMAT_WORDS,
            bm + l * H, br + l * H, p_m16, p_pre);
        // pre += sum_in sigmoid(...)*m[src]; fused LN stats
        gather_kernel<<<2048, 256>>>(N, p_a, ba + l, p_m16, p_pre,
                                     p_stats + l * 2 * H);
    }

    // pool = segment_sum(LN(pre_3)); restores g_deg
    pool_kernel<<<rowBlocks, 256>>>(N, invN, p_pre, p_stats + 3 * 2 * H,
                                    gamma + 3 * H, beta + 3 * H, batch, p_pool);
    // head; restores g_pool/g_stats
    head_kernel<<<1, 256>>>(p_pool, W1, b1, W2, b2, (float*)d_out, p_stats);
}

// round 13
// speedup vs baseline: 1.5521x; 1.0488x over previous
#include <cuda_runtime.h>
#include <cuda_fp16.h>
#include <math.h>
#include <stdint.h>

#define H 128
#define LYR 4
#define G 64
#define C 10
#define MAXN 50048
#define MAXE 600064
#define EPSV 1e-5f

// Persistent device scratch (static, no allocation).
// INVARIANT: g_deg, g_pool, g_stats are zero at entry (zero-initialized .bss;
// restored to zero by pool_kernel / head_kernel at the end of every call).
__device__ __align__(16) float g_h[MAXN * H];
__device__ __align__(16) uint32_t g_m16[MAXN * 64];   // m in half2, 64 words/row
__device__ __align__(16) float g_pre[MAXN * H];
__device__ __align__(16) float g_a[MAXN * 2];
__device__ __align__(16) float g_stats[LYR * 2 * H];
__device__ __align__(16) float g_pool[G * H];
__device__ int g_deg[MAXN];
__device__ int g_off[MAXN];
__device__ int g_cursor[MAXN];
__device__ int g_adj[MAXE];          // src node per CSR slot
__device__ int g_btot[32];
// 9 matrices, each: hi half + lo half (unscaled fp16 residual)
#define SROW 136
#define HALF_WORDS (64 * SROW)                // 8704 words (one 128x128 f16 image)
#define BMAT_WORDS (2 * HALF_WORDS)
__device__ __align__(16) uint32_t g_Bsplit[9 * BMAT_WORDS];

static inline int cdiv(int a, int b) { return (a + b - 1) / b; }

// ---------------------------------------------------------------------------
// fp16 helpers
// ---------------------------------------------------------------------------
__device__ __forceinline__ uint32_t pack_h2(float f0, float f1) {
    __half2 h = __floats2half2_rn(f0, f1);
    return *(uint32_t*)&h;
}

__device__ __forceinline__ void mma16816(float* d, const uint32_t* a,
                                         const uint32_t* b) {
    asm volatile(
        "mma.sync.aligned.m16n8k16.row.col.f32.f16.f16.f32 "
        "{%0,%1,%2,%3}, {%4,%5,%6,%7}, {%8,%9}, {%0,%1,%2,%3};\n"
        : "+f"(d[0]), "+f"(d[1]), "+f"(d[2]), "+f"(d[3])
        : "r"(a[0]), "r"(a[1]), "r"(a[2]), "r"(a[3]),
          "r"(b[0]), "r"(b[1]));
}

// ---------------------------------------------------------------------------
// Fused prep (blockIdx.y == 0..8 -> weight split) + edge count (y == 9).
// ---------------------------------------------------------------------------
__global__ __launch_bounds__(256) void prep_count_kernel(
    const float* __restrict__ W_in, const float* __restrict__ Wm,
    const float* __restrict__ Wr, int E, const int* __restrict__ dst,
    int countBlocks)
{
    if (blockIdx.y < 9) {
        int mat = blockIdx.y;
        if (blockIdx.x >= 32) return;
        const float* W = (mat == 0) ? W_in
                       : (mat < 5) ? Wm + (mat - 1) * H * H
                                   : Wr + (mat - 5) * H * H;
        uint32_t* out = g_Bsplit + mat * BMAT_WORDS;
        int p = blockIdx.x * 256 + threadIdx.x;
        int n = p >> 6;
        int kp = p & 63;
        int k = kp * 2;
        float f0 = W[k * H + n];
        float f1 = W[(k + 1) * H + n];
        __half h0 = __float2half_rn(f0);
        __half h1 = __float2half_rn(f1);
        float r0 = f0 - __half2float(h0);
        float r1 = f1 - __half2float(h1);
        out[kp * SROW + n] = pack_h2(__half2float(h0), __half2float(h1));
        out[HALF_WORDS + kp * SROW + n] = pack_h2(r0, r1);
    } else {
        int i = blockIdx.x * 256 + threadIdx.x;
        if (i < E) atomicAdd(&g_deg[dst[i]], 1);
    }
}

// ---------------------------------------------------------------------------
// GEMM building blocks (fp16, A single image, B hi+lo, ONE accumulator)
// ---------------------------------------------------------------------------
#define PERS1_SMEM (3 * HALF_WORDS * 4)       // 104448 B (A + one B pair)
#define PERS2_SMEM (5 * HALF_WORDS * 4)       // 174080 B (A + two B pairs)
#define GRID_PERS 148

__device__ __forceinline__ void gemm_copyB(uint32_t* dstB, const uint32_t* Bimg,
                                           int tid) {
    uint4* bs = (uint4*)dstB;
    const uint4* bg = (const uint4*)Bimg;
#pragma unroll
    for (int i = 0; i < 17; i++)
        bs[tid + i * 256] = bg[tid + i * 256];
}

// Convert A tile (raw fp32, optional affine LN + relu) to fp16 image;
// fused adot partials.
__device__ __forceinline__ void gemm_cvtA(uint32_t* Ah, const float* Araw,
    int M, int rowBase, int tid,
    const float* s_scale, const float* s_shift,
    const float* s_ws, const float* s_wd,
    float (*s_pdS)[128], float (*s_pdD)[128])
{
    int row = tid & 127;
    int khalf = tid >> 7;
    bool ok = (rowBase + row) < M;
    const float4* Ar = (const float4*)(Araw + (size_t)(rowBase + row) * 128 + khalf * 64);
    float ss = 0.f, sd = 0.f;
#pragma unroll
    for (int i = 0; i < 16; i++) {
        float4 p = ok ? Ar[i] : make_float4(0.f, 0.f, 0.f, 0.f);
        int k = khalf * 64 + i * 4;
        float4 v;
        v.x = fmaxf(p.x * s_scale[k + 0] + s_shift[k + 0], 0.f);
        v.y = fmaxf(p.y * s_scale[k + 1] + s_shift[k + 1], 0.f);
        v.z = fmaxf(p.z * s_scale[k + 2] + s_shift[k + 2], 0.f);
        v.w = fmaxf(p.w * s_scale[k + 3] + s_shift[k + 3], 0.f);
        if (!ok) { v.x = 0.f; v.y = 0.f; v.z = 0.f; v.w = 0.f; }
        ss += v.x * s_ws[k] + v.y * s_ws[k + 1] + v.z * s_ws[k + 2] + v.w * s_ws[k + 3];
        sd += v.x * s_wd[k] + v.y * s_wd[k + 1] + v.z * s_wd[k + 2] + v.w * s_wd[k + 3];
        int kp = khalf * 32 + i * 2;
        Ah[kp * SROW + row]       = pack_h2(v.x, v.y);
        Ah[(kp + 1) * SROW + row] = pack_h2(v.z, v.w);
    }
    s_pdS[khalf][row] = ss;
    s_pdD[khalf][row] = sd;
}

// Plain convert (no LN, no adot) for the input GEMM
__device__ __forceinline__ void gemm_cvtA_plain(uint32_t* Ah, const float* Araw,
                                                int M, int rowBase, int tid)
{
    int row = tid & 127;
    int khalf = tid >> 7;
    bool ok = (rowBase + row) < M;
    const float4* Ar = (const float4*)(Araw + (size_t)(rowBase + row) * 128 + khalf * 64);
#pragma unroll
    for (int i = 0; i < 16; i++) {
        float4 v = ok ? Ar[i] : make_float4(0.f, 0.f, 0.f, 0.f);
        int kp = khalf * 32 + i * 2;
        Ah[kp * SROW + row]       = pack_h2(v.x, v.y);
        Ah[(kp + 1) * SROW + row] = pack_h2(v.z, v.w);
    }
}

// Single-accumulator compute: acc += A*B_hi + A*B_lo
__device__ __forceinline__ void gemm_compute(const uint32_t* Ah,
    const uint32_t* Bb, int warp_m, int warp_n, int g, int tg,
    float acc[2][8][4])
{
#pragma unroll
    for (int mi = 0; mi < 2; mi++)
#pragma unroll
        for (int ni = 0; ni < 8; ni++)
#pragma unroll
            for (int q = 0; q < 4; q++) acc[mi][ni][q] = 0.f;

#pragma unroll
    for (int s = 0; s < 8; s++) {
        int q0 = s * 8 + tg;
        int q1 = s * 8 + 4 + tg;
        uint32_t a[2][4];
#pragma unroll
        for (int mi = 0; mi < 2; mi++) {
            int r0 = warp_m + mi * 16 + g;
            a[mi][0] = Ah[q0 * SROW + r0];
            a[mi][1] = Ah[q0 * SROW + r0 + 8];
            a[mi][2] = Ah[q1 * SROW + r0];
            a[mi][3] = Ah[q1 * SROW + r0 + 8];
        }
#pragma unroll
        for (int ni = 0; ni < 8; ni++) {
            int cn = warp_n + ni * 8 + g;
            uint32_t bhi[2], blo[2];
            bhi[0] = Bb[q0 * SROW + cn];
            bhi[1] = Bb[q1 * SROW + cn];
            blo[0] = Bb[HALF_WORDS + q0 * SROW + cn];
            blo[1] = Bb[HALF_WORDS + q1 * SROW + cn];
#pragma unroll
            for (int mi = 0; mi < 2; mi++) {
                mma16816(acc[mi][ni], a[mi], bhi);
                mma16816(acc[mi][ni], a[mi], blo);
            }
        }
    }
}

// fp32 store (pre / h outputs)
__device__ __forceinline__ void gemm_store(float acc[2][8][4],
    const float* __restrict__ bias, float* __restrict__ Cm,
    int M, int rowBase, int warp_m, int warp_n, int g, int tg, int relu)
{
    float bv[8][2];
#pragma unroll
    for (int ni = 0; ni < 8; ni++) {
        int cb = warp_n + ni * 8 + 2 * tg;
        bv[ni][0] = bias[cb];
        bv[ni][1] = bias[cb + 1];
    }
#pragma unroll
    for (int mi = 0; mi < 2; mi++) {
#pragma unroll
        for (int rh = 0; rh < 2; rh++) {
            int row = rowBase + warp_m + mi * 16 + g + rh * 8;
            if (row < M) {
#pragma unroll
                for (int ni = 0; ni < 8; ni++) {
                    float vx = acc[mi][ni][rh * 2 + 0] + bv[ni][0];
                    float vy = acc[mi][ni][rh * 2 + 1] + bv[ni][1];
                    if (relu) { vx = fmaxf(vx, 0.f); vy = fmaxf(vy, 0.f); }
                    float2 o; o.x = vx; o.y = vy;
                    *(float2*)(Cm + (size_t)row * 128 + warp_n + ni * 8 + 2 * tg) = o;
                }
            }
        }
    }
}

// fp16 store (m output): pack two adjacent cols into one half2 word
__device__ __forceinline__ void gemm_store_m16(float acc[2][8][4],
    const float* __restrict__ bias, uint32_t* __restrict__ Cm16,
    int M, int rowBase, int warp_m, int warp_n, int g, int tg)
{
    float bv[8][2];
#pragma unroll
    for (int ni = 0; ni < 8; ni++) {
        int cb = warp_n + ni * 8 + 2 * tg;
        bv[ni][0] = bias[cb];
        bv[ni][1] = bias[cb + 1];
    }
#pragma unroll
    for (int mi = 0; mi < 2; mi++) {
#pragma unroll
        for (int rh = 0; rh < 2; rh++) {
            int row = rowBase + warp_m + mi * 16 + g + rh * 8;
            if (row < M) {
#pragma unroll
                for (int ni = 0; ni < 8; ni++) {
                    float vx = acc[mi][ni][rh * 2 + 0] + bv[ni][0];
                    float vy = acc[mi][ni][rh * 2 + 1] + bv[ni][1];
                    int col = warp_n + ni * 8 + 2 * tg;
                    Cm16[(size_t)row * 64 + (col >> 1)] = pack_h2(vx, vy);
                }
            }
        }
    }
}

// Persistent single GEMM (input layer): C = relu(A @ W + b). B copied once.
__global__ __launch_bounds__(256) void pers_gemm(
    int M, const float* __restrict__ A, const uint32_t* __restrict__ Bimg,
    const float* __restrict__ bias, float* __restrict__ Cm, int relu)
{
    extern __shared__ uint32_t sm[];
    uint32_t* Ah = sm;
    uint32_t* Bb = sm + HALF_WORDS;

    int tid = threadIdx.x;
    int warp = tid >> 5, lane = tid & 31;
    int g = lane >> 2, tg = lane & 3;
    int warp_m = (warp >> 1) * 32;
    int warp_n = (warp & 1) * 64;
    int ntiles = (M + 127) >> 7;

    gemm_copyB(Bb, Bimg, tid);

    for (int tile = blockIdx.x; tile < ntiles; tile += gridDim.x) {
        __syncthreads();
        gemm_cvtA_plain(Ah, A, M, tile * 128, tid);
        __syncthreads();
        float acc[2][8][4];
        gemm_compute(Ah, Bb, warp_m, warp_n, g, tg, acc);
        gemm_store(acc, bias, Cm, M, tile * 128, warp_m, warp_n, g, tg, relu);
    }
}

// ---------------------------------------------------------------------------
// Persistent dual GEMM with fused input-normalization and adot.
// m output in fp16 (half2), pre output fp32.
// ---------------------------------------------------------------------------
__global__ __launch_bounds__(256) void pers_dual_gemm(
    int M, float invN, const float* __restrict__ Araw, int useLN,
    const float* __restrict__ stats,
    const float* __restrict__ gamma, const float* __restrict__ beta,
    const float* __restrict__ Wa_l, float* __restrict__ a_out,
    const uint32_t* __restrict__ Bm_img, const uint32_t* __restrict__ Br_img,
    const float* __restrict__ bm, const float* __restrict__ br,
    uint32_t* __restrict__ Cm16, float* __restrict__ Cpre)
{
    extern __shared__ uint32_t sm[];
    uint32_t* Ah  = sm;
    uint32_t* Bmb = sm + HALF_WORDS;
    uint32_t* Brb = sm + 3 * HALF_WORDS;
    __shared__ float s_scale[128], s_shift[128];
    __shared__ float s_ws[128], s_wd[128];
    __shared__ float s_pdS[2][128], s_pdD[2][128];

    int tid = threadIdx.x;
    int warp = tid >> 5, lane = tid & 31;
    int g = lane >> 2, tg = lane & 3;
    int warp_m = (warp >> 1) * 32;
    int warp_n = (warp & 1) * 64;
    int ntiles = (M + 127) >> 7;

    if (tid < 128) {
        float sc = 1.f, sh = 0.f;
        if (useLN) {
            float s = stats[tid], q = stats[128 + tid];
            float mu = s * invN;
            float var = q * invN - mu * mu;
            float rs = rsqrtf(var + EPSV);
            sc = rs * gamma[tid];
            sh = beta[tid] - mu * sc;
        }
        s_scale[tid] = sc;
        s_shift[tid] = sh;
        s_ws[tid] = Wa_l[tid];
        s_wd[tid] = Wa_l[128 + tid];
    }
    gemm_copyB(Bmb, Bm_img, tid);
    gemm_copyB(Brb, Br_img, tid);

    for (int tile = blockIdx.x; tile < ntiles; tile += gridDim.x) {
        int rowBase = tile * 128;
        __syncthreads();   // B/scale ready; prev iter compute + a_out done
        gemm_cvtA(Ah, Araw, M, rowBase, tid, s_scale, s_shift, s_ws, s_wd,
                  s_pdS, s_pdD);
        __syncthreads();
        if (tid < 128 && rowBase + tid < M) {
            a_out[2 * (rowBase + tid)]     = s_pdS[0][tid] + s_pdS[1][tid];
            a_out[2 * (rowBase + tid) + 1] = s_pdD[0][tid] + s_pdD[1][tid];
        }
        {
            float acc[2][8][4];
            gemm_compute(Ah, Bmb, warp_m, warp_n, g, tg, acc);
            gemm_store_m16(acc, bm, Cm16, M, rowBase, warp_m, warp_n, g, tg);
        }
        {
            float acc[2][8][4];
            gemm_compute(Ah, Brb, warp_m, warp_n, g, tg, acc);
            gemm_store(acc, br, Cpre, M, rowBase, warp_m, warp_n, g, tg, 0);
        }
    }
}

// ---------------------------------------------------------------------------
// CSR build: scan + fill (count fused into prep_count_kernel)
// ---------------------------------------------------------------------------
#define SCB 4096   // elements per scan block (256 thr x 16)

__global__ __launch_bounds__(256) void scan1_kernel(int N) {
    __shared__ int wsum[8];
    int tid = threadIdx.x;
    int lane = tid & 31, w = tid >> 5;
    int base = blockIdx.x * SCB + tid * 16;
    int v[16];
    int s = 0;
#pragma unroll
    for (int i = 0; i < 16; i++) {
        int idx = base + i;
        v[i] = (idx < N) ? g_deg[idx] : 0;
        s += v[i];
    }
    int incl = s;
#pragma unroll
    for (int d = 1; d < 32; d <<= 1) {
        int t = __shfl_up_sync(0xFFFFFFFFu, incl, d);
        if (lane >= d) incl += t;
    }
    if (lane == 31) wsum[w] = incl;
    __syncthreads();
    if (tid == 0) {
        int c = 0;
#pragma unroll
        for (int i = 0; i < 8; i++) { int x = wsum[i]; wsum[i] = c; c += x; }
        g_btot[blockIdx.x] = c;
    }
    __syncthreads();
    int run = incl - s + wsum[w];
#pragma unroll
    for (int i = 0; i < 16; i++) {
        int idx = base + i;
        if (idx < N) g_off[idx] = run;
        run += v[i];
    }
}

// scan3: adds inline prefix of block totals (nb <= 13)
__global__ __launch_bounds__(256) void scan3_kernel(int N) {
    int i = blockIdx.x * 256 + threadIdx.x;
    if (i < N) {
        int b = i / SCB;
        int add = 0;
        for (int j = 0; j < b; j++) add += g_btot[j];
        int o = g_off[i] + add;
        g_off[i] = o;
        g_cursor[i] = o;
    }
}

__global__ __launch_bounds__(256) void fill_kernel(
    int E, const int* __restrict__ src, const int* __restrict__ dst)
{
    int i = blockIdx.x * 256 + threadIdx.x;
    if (i < E) {
        int slot = atomicAdd(&g_cursor[dst[i]], 1);
        g_adj[slot] = src[i];
    }
}

// ---------------------------------------------------------------------------
// Gather: pre[d] += sum_in sigmoid(a_src[s]+a_dst[d]+ba)*m[s]
// CSR, warp per row, 4-edge ILP batches (MLP~4). Fused LN stats.
// ---------------------------------------------------------------------------
__global__ __launch_bounds__(256) void gather_kernel(
    int N, const float* __restrict__ a, const float* __restrict__ ba_l,
    const uint32_t* __restrict__ m16, float* __restrict__ pre,
    float* __restrict__ stats)
{
    __shared__ float redS[8][128], redQ[8][128];
    int tid = threadIdx.x;
    int w = tid >> 5, lane = tid & 31;
    float bav = ba_l[0];
    float4 s1 = make_float4(0.f, 0.f, 0.f, 0.f);
    float4 s2 = make_float4(0.f, 0.f, 0.f, 0.f);
    const uint2* m2 = (const uint2*)m16;   // 32 uint2 per row

    for (int row = blockIdx.x * 8 + w; row < N; row += gridDim.x * 8) {
        float4 v = ((const float4*)pre)[row * 32 + lane];
        float ad = a[2 * row + 1] + bav;
        int off = g_off[row];
        int deg = g_deg[row];
        const int* ep = g_adj + off;

        int e = 0;
        // --- 4-edge batches: all loads issued before any use (MLP ~4-5) ---
        for (; e + 4 <= deg; e += 4) {
            int sA = ep[e], sB = ep[e + 1], sC = ep[e + 2], sD = ep[e + 3];
            float zA = a[2 * sA], zB = a[2 * sB];
            float zC = a[2 * sC], zD = a[2 * sD];
            uint2 mA = m2[(size_t)sA * 32 + lane];
            uint2 mB = m2[(size_t)sB * 32 + lane];
            uint2 mC = m2[(size_t)sC * 32 + lane];
            uint2 mD = m2[(size_t)sD * 32 + lane];
            float gA = 1.f / (1.f + __expf(-(zA + ad)));
            float gB = 1.f / (1.f + __expf(-(zB + ad)));
            float gC = 1.f / (1.f + __expf(-(zC + ad)));
            float gD = 1.f / (1.f + __expf(-(zD + ad)));
            float2 lo, hi;
            lo = __half22float2(*(__half2*)&mA.x); hi = __half22float2(*(__half2*)&mA.y);
            v.x += gA * lo.x; v.y += gA * lo.y; v.z += gA * hi.x; v.w += gA * hi.y;
            lo = __half22float2(*(__half2*)&mB.x); hi = __half22float2(*(__half2*)&mB.y);
            v.x += gB * lo.x; v.y += gB * lo.y; v.z += gB * hi.x; v.w += gB * hi.y;
            lo = __half22float2(*(__half2*)&mC.x); hi = __half22float2(*(__half2*)&mC.y);
            v.x += gC * lo.x; v.y += gC * lo.y; v.z += gC * hi.x; v.w += gC * hi.y;
            lo = __half22float2(*(__half2*)&mD.x); hi = __half22float2(*(__half2*)&mD.y);
            v.x += gD * lo.x; v.y += gD * lo.y; v.z += gD * hi.x; v.w += gD * hi.y;
        }
        // --- remainder ---
        for (; e < deg; e++) {
            int sA = ep[e];
            float zA = a[2 * sA];
            uint2 mA = m2[(size_t)sA * 32 + lane];
            float gA = 1.f / (1.f + __expf(-(zA + ad)));
            float2 lo = __half22float2(*(__half2*)&mA.x);
            float2 hi = __half22float2(*(__half2*)&mA.y);
            v.x += gA * lo.x; v.y += gA * lo.y;
            v.z += gA * hi.x; v.w += gA * hi.y;
        }

        ((float4*)pre)[row * 32 + lane] = v;
        s1.x += v.x; s1.y += v.y; s1.z += v.z; s1.w += v.w;
        s2.x += v.x * v.x; s2.y += v.y * v.y;
        s2.z += v.z * v.z; s2.w += v.w * v.w;
    }
    *(float4*)&redS[w][lane * 4] = s1;
    *(float4*)&redQ[w][lane * 4] = s2;
    __syncthreads();
    if (tid < 128) {
        float aa = 0.f, bb = 0.f;
#pragma unroll
        for (int i = 0; i < 8; i++) { aa += redS[i][tid]; bb += redQ[i][tid]; }
        atomicAdd(&stats[tid], aa);
        atomicAdd(&stats[128 + tid], bb);
    }
}

// ---------------------------------------------------------------------------
// Final pool: normalize pre (layer 3) on the fly and pool. Warp per row.
// Also restores g_deg = 0 (state invariant for the next call).
// ---------------------------------------------------------------------------
__global__ __launch_bounds__(256) void pool_kernel(
    int N, float invN, const float* __restrict__ pre,
    const float* __restrict__ stats,
    const float* __restrict__ gamma, const float* __restrict__ beta,
    const int* __restrict__ batch, float* __restrict__ pool)
{
    int tid = threadIdx.x;
    int w = tid >> 5, lane = tid & 31;
    float sc[4], sh[4];
#pragma unroll
    for (int i = 0; i < 4; i++) {
        int c = lane * 4 + i;
        float s = stats[c], q = stats[128 + c];
        float mu = s * invN;
        float var = q * invN - mu * mu;
        float rs = rsqrtf(var + EPSV);
        sc[i] = rs * gamma[c];
        sh[i] = beta[c] - mu * sc[i];
    }
    for (int row = blockIdx.x * 8 + w; row < N; row += gridDim.x * 8) {
        float4 p = ((const float4*)pre)[row * 32 + lane];
        float4 v;
        v.x = fmaxf(p.x * sc[0] + sh[0], 0.f);
        v.y = fmaxf(p.y * sc[1] + sh[1], 0.f);
        v.z = fmaxf(p.z * sc[2] + sh[2], 0.f);
        v.w = fmaxf(p.w * sc[3] + sh[3], 0.f);
        int b = batch[row];
        atomicAdd(((float4*)(pool + (size_t)b * 128)) + lane, v);
        if (lane == 0) g_deg[row] = 0;     // restore invariant
    }
}

// ---------------------------------------------------------------------------
// MLP head; restores g_pool and g_stats to zero (state invariant).
// ---------------------------------------------------------------------------
__global__ __launch_bounds__(256) void head_kernel(
    float* __restrict__ pool,
    const float* __restrict__ W1, const float* __restrict__ b1,
    const float* __restrict__ W2, const float* __restrict__ b2,
    float* __restrict__ out, float* __restrict__ stats)
{
    __shared__ float sh[G * 64];
    int tid = threadIdx.x;
    for (int o = tid; o < G * 64; o += 256) {
        int g = o >> 6, j = o & 63;
        float s = b1[j];
        const float* pr = pool + g * 128;
#pragma unroll 4
        for (int k = 0; k < 128; k++) s += pr[k] * W1[k * 64 + j];
        sh[o] = fmaxf(s, 0.f);
    }
    __syncthreads();            // all reads of pool complete
    for (int o = tid; o < G * H; o += 256) pool[o] = 0.f;
    for (int o = tid; o < LYR * 2 * H; o += 256) stats[o] = 0.f;
    for (int o = tid; o < G * C; o += 256) {
        int g = o / C, c = o % C;
        float s = b2[c];
        const float* hr = sh + g * 64;
#pragma unroll 4
        for (int k = 0; k < 64; k++) s += hr[k] * W2[k * C + c];
        out[o] = s * 0.5f;   // /TEMP
    }
}

// ---------------------------------------------------------------------------
// Launch
// ---------------------------------------------------------------------------
extern "C" void kernel_launch(void* const* d_in, const int* in_sizes, int n_in,
                              void* d_out, int out_size)
{
    const float* x     = (const float*)d_in[0];
    const int*   ei    = (const int*)d_in[1];
    const int*   batch = (const int*)d_in[2];
    const float* W_in  = (const float*)d_in[3];
    const float* b_in  = (const float*)d_in[4];
    const float* Wa    = (const float*)d_in[5];
    const float* ba    = (const float*)d_in[6];
    const float* Wm    = (const float*)d_in[7];
    const float* bm    = (const float*)d_in[8];
    const float* Wr    = (const float*)d_in[9];
    const float* br    = (const float*)d_in[10];
    const float* gamma = (const float*)d_in[11];
    const float* beta  = (const float*)d_in[12];
    const float* W1    = (const float*)d_in[13];
    const float* b1    = (const float*)d_in[14];
    const float* W2    = (const float*)d_in[15];
    const float* b2    = (const float*)d_in[16];

    int N = in_sizes[0] / 128;
    int E = in_sizes[1] / 2;
    const int* src = ei;
    const int* dst = ei + E;

    cudaFuncSetAttribute(pers_gemm, cudaFuncAttributeMaxDynamicSharedMemorySize,
                         PERS1_SMEM);
    cudaFuncSetAttribute(pers_dual_gemm, cudaFuncAttributeMaxDynamicSharedMemorySize,
                         PERS2_SMEM);

    float *p_h, *p_pre, *p_a, *p_pool, *p_stats;
    uint32_t *p_m16, *p_B;
    cudaGetSymbolAddress((void**)&p_h, g_h);
    cudaGetSymbolAddress((void**)&p_m16, g_m16);
    cudaGetSymbolAddress((void**)&p_pre, g_pre);
    cudaGetSymbolAddress((void**)&p_a, g_a);
    cudaGetSymbolAddress((void**)&p_pool, g_pool);
    cudaGetSymbolAddress((void**)&p_stats, g_stats);
    cudaGetSymbolAddress((void**)&p_B, g_Bsplit);

    int rowBlocks = cdiv(N, 8);
    int scanBlocks = cdiv(N, SCB);
    int countBlocks = cdiv(E, 256);
    float invN = 1.0f / (float)N;

    // --- one-time per call: fused weights prep + count, then scan + fill ---
    prep_count_kernel<<<dim3(countBlocks, 10), 256>>>(W_in, Wm, Wr, E, dst,
                                                      countBlocks);
    scan1_kernel<<<scanBlocks, 256>>>(N);
    scan3_kernel<<<cdiv(N, 256), 256>>>(N);
    fill_kernel<<<countBlocks, 256>>>(E, src, dst);

    // h = relu(x @ W_in + b_in)
    pers_gemm<<<GRID_PERS, 256, PERS1_SMEM>>>(N, x, p_B, b_in, p_h, 1);

    for (int l = 0; l < LYR; l++) {
        // A = (l==0) ? h (identity) : pre (inline LN+relu). Fused next adot.
        pers_dual_gemm<<<GRID_PERS, 256, PERS2_SMEM>>>(
            N, invN,
            (l == 0) ? p_h : p_pre, (l == 0) ? 0 : 1,
            p_stats + (l - 1) * 2 * H,
            gamma + (l - 1) * H, beta + (l - 1) * H,
            Wa + l * 2 * H, p_a,
            p_B + (1 + l) * BMAT_WORDS, p_B + (5 + l) * BMAT_WORDS,
            bm + l * H, br + l * H, p_m16, p_pre);
        // pre += sum_in sigmoid(...)*m[src]; fused LN stats
        gather_kernel<<<2048, 256>>>(N, p_a, ba + l, p_m16, p_pre,
                                     p_stats + l * 2 * H);
    }

    // pool = segment_sum(LN(pre_3)); restores g_deg
    pool_kernel<<<rowBlocks, 256>>>(N, invN, p_pre, p_stats + 3 * 2 * H,
                                    gamma + 3 * H, beta + 3 * H, batch, p_pool);
    // head; restores g_pool/g_stats
    head_kernel<<<1, 256>>>(p_pool, W1, b1, W2, b2, (float*)d_out, p_stats);
}

// round 14
// speedup vs baseline: 1.6122x; 1.0387x over previous
#include <cuda_runtime.h>
#include <cuda_fp16.h>
#include <math.h>
#include <stdint.h>

#define H 128
#define LYR 4
#define G 64
#define C 10
#define MAXN 50048
#define MAXE 600064
#define EPSV 1e-5f

// Persistent device scratch (static, no allocation).
// INVARIANT: g_deg, g_pool, g_stats are zero at entry (zero-initialized .bss;
// restored to zero by pool_kernel / head_kernel at the end of every call).
__device__ __align__(16) uint32_t g_h16[MAXN * 64];    // h  in half2
__device__ __align__(16) uint32_t g_m16[MAXN * 64];    // m  in half2
__device__ __align__(16) uint32_t g_pre16[MAXN * 64];  // pre in half2
__device__ __align__(16) float g_a[MAXN * 2];
__device__ __align__(16) float g_stats[LYR * 2 * H];
__device__ __align__(16) float g_pool[G * H];
__device__ int g_deg[MAXN];
__device__ int g_off[MAXN];
__device__ int g_cursor[MAXN];
__device__ int g_adj[MAXE];          // src node per CSR slot
__device__ int g_btot[32];
// 9 matrices, each: hi half + lo half (unscaled fp16 residual)
#define SROW 136
#define HALF_WORDS (64 * SROW)                // 8704 words (one 128x128 f16 image)
#define BMAT_WORDS (2 * HALF_WORDS)
__device__ __align__(16) uint32_t g_Bsplit[9 * BMAT_WORDS];

static inline int cdiv(int a, int b) { return (a + b - 1) / b; }

// ---------------------------------------------------------------------------
// fp16 helpers
// ---------------------------------------------------------------------------
__device__ __forceinline__ uint32_t pack_h2(float f0, float f1) {
    __half2 h = __floats2half2_rn(f0, f1);
    return *(uint32_t*)&h;
}
__device__ __forceinline__ float2 unpack_h2(uint32_t w) {
    return __half22float2(*(const __half2*)&w);
}

__device__ __forceinline__ void mma16816(float* d, const uint32_t* a,
                                         const uint32_t* b) {
    asm volatile(
        "mma.sync.aligned.m16n8k16.row.col.f32.f16.f16.f32 "
        "{%0,%1,%2,%3}, {%4,%5,%6,%7}, {%8,%9}, {%0,%1,%2,%3};\n"
        : "+f"(d[0]), "+f"(d[1]), "+f"(d[2]), "+f"(d[3])
        : "r"(a[0]), "r"(a[1]), "r"(a[2]), "r"(a[3]),
          "r"(b[0]), "r"(b[1]));
}

// ---------------------------------------------------------------------------
// Fused prep (blockIdx.y == 0..8 -> weight split) + edge count (y == 9).
// ---------------------------------------------------------------------------
__global__ __launch_bounds__(256) void prep_count_kernel(
    const float* __restrict__ W_in, const float* __restrict__ Wm,
    const float* __restrict__ Wr, int E, const int* __restrict__ dst)
{
    if (blockIdx.y < 9) {
        int mat = blockIdx.y;
        if (blockIdx.x >= 32) return;
        const float* W = (mat == 0) ? W_in
                       : (mat < 5) ? Wm + (mat - 1) * H * H
                                   : Wr + (mat - 5) * H * H;
        uint32_t* out = g_Bsplit + mat * BMAT_WORDS;
        int p = blockIdx.x * 256 + threadIdx.x;
        int n = p >> 6;
        int kp = p & 63;
        int k = kp * 2;
        float f0 = W[k * H + n];
        float f1 = W[(k + 1) * H + n];
        __half h0 = __float2half_rn(f0);
        __half h1 = __float2half_rn(f1);
        float r0 = f0 - __half2float(h0);
        float r1 = f1 - __half2float(h1);
        out[kp * SROW + n] = pack_h2(__half2float(h0), __half2float(h1));
        out[HALF_WORDS + kp * SROW + n] = pack_h2(r0, r1);
    } else {
        int i = blockIdx.x * 256 + threadIdx.x;
        if (i < E) atomicAdd(&g_deg[dst[i]], 1);
    }
}

// ---------------------------------------------------------------------------
// GEMM building blocks (fp16, A single image, B hi+lo, ONE accumulator)
// ---------------------------------------------------------------------------
#define PERS1_SMEM (3 * HALF_WORDS * 4)       // 104448 B (A + one B pair)
#define PERS2_SMEM (5 * HALF_WORDS * 4)       // 174080 B (A + two B pairs)
#define GRID_PERS 148

__device__ __forceinline__ void gemm_copyB(uint32_t* dstB, const uint32_t* Bimg,
                                           int tid) {
    uint4* bs = (uint4*)dstB;
    const uint4* bg = (const uint4*)Bimg;
#pragma unroll
    for (int i = 0; i < 17; i++)
        bs[tid + i * 256] = bg[tid + i * 256];
}

// Convert A tile (fp16 half2 input, affine LN + relu) to fp16 smem image;
// fused adot partials. Identity transform when scale=1/shift=0.
__device__ __forceinline__ void gemm_cvtA16(uint32_t* Ah,
    const uint32_t* __restrict__ A16,
    int M, int rowBase, int tid,
    const float* s_scale, const float* s_shift,
    const float* s_ws, const float* s_wd,
    float (*s_pdS)[128], float (*s_pdD)[128])
{
    int row = tid & 127;
    int khalf = tid >> 7;
    bool ok = (rowBase + row) < M;
    const uint2* Ar = (const uint2*)(A16 + (size_t)(rowBase + row) * 64 + khalf * 32);
    float ss = 0.f, sd = 0.f;
#pragma unroll
    for (int i = 0; i < 16; i++) {
        uint2 w = ok ? Ar[i] : make_uint2(0u, 0u);
        float2 p0 = unpack_h2(w.x);
        float2 p1 = unpack_h2(w.y);
        int k = khalf * 64 + i * 4;
        float4 v;
        v.x = fmaxf(p0.x * s_scale[k + 0] + s_shift[k + 0], 0.f);
        v.y = fmaxf(p0.y * s_scale[k + 1] + s_shift[k + 1], 0.f);
        v.z = fmaxf(p1.x * s_scale[k + 2] + s_shift[k + 2], 0.f);
        v.w = fmaxf(p1.y * s_scale[k + 3] + s_shift[k + 3], 0.f);
        if (!ok) { v.x = 0.f; v.y = 0.f; v.z = 0.f; v.w = 0.f; }
        ss += v.x * s_ws[k] + v.y * s_ws[k + 1] + v.z * s_ws[k + 2] + v.w * s_ws[k + 3];
        sd += v.x * s_wd[k] + v.y * s_wd[k + 1] + v.z * s_wd[k + 2] + v.w * s_wd[k + 3];
        int kp = khalf * 32 + i * 2;
        Ah[kp * SROW + row]       = pack_h2(v.x, v.y);
        Ah[(kp + 1) * SROW + row] = pack_h2(v.z, v.w);
    }
    s_pdS[khalf][row] = ss;
    s_pdD[khalf][row] = sd;
}

// Plain convert (fp32 in, no LN, no adot) for the input GEMM
__device__ __forceinline__ void gemm_cvtA_plain(uint32_t* Ah, const float* Araw,
                                                int M, int rowBase, int tid)
{
    int row = tid & 127;
    int khalf = tid >> 7;
    bool ok = (rowBase + row) < M;
    const float4* Ar = (const float4*)(Araw + (size_t)(rowBase + row) * 128 + khalf * 64);
#pragma unroll
    for (int i = 0; i < 16; i++) {
        float4 v = ok ? Ar[i] : make_float4(0.f, 0.f, 0.f, 0.f);
        int kp = khalf * 32 + i * 2;
        Ah[kp * SROW + row]       = pack_h2(v.x, v.y);
        Ah[(kp + 1) * SROW + row] = pack_h2(v.z, v.w);
    }
}

// Single-accumulator compute: acc += A*B_hi + A*B_lo
__device__ __forceinline__ void gemm_compute(const uint32_t* Ah,
    const uint32_t* Bb, int warp_m, int warp_n, int g, int tg,
    float acc[2][8][4])
{
#pragma unroll
    for (int mi = 0; mi < 2; mi++)
#pragma unroll
        for (int ni = 0; ni < 8; ni++)
#pragma unroll
            for (int q = 0; q < 4; q++) acc[mi][ni][q] = 0.f;

#pragma unroll
    for (int s = 0; s < 8; s++) {
        int q0 = s * 8 + tg;
        int q1 = s * 8 + 4 + tg;
        uint32_t a[2][4];
#pragma unroll
        for (int mi = 0; mi < 2; mi++) {
            int r0 = warp_m + mi * 16 + g;
            a[mi][0] = Ah[q0 * SROW + r0];
            a[mi][1] = Ah[q0 * SROW + r0 + 8];
            a[mi][2] = Ah[q1 * SROW + r0];
            a[mi][3] = Ah[q1 * SROW + r0 + 8];
        }
#pragma unroll
        for (int ni = 0; ni < 8; ni++) {
            int cn = warp_n + ni * 8 + g;
            uint32_t bhi[2], blo[2];
            bhi[0] = Bb[q0 * SROW + cn];
            bhi[1] = Bb[q1 * SROW + cn];
            blo[0] = Bb[HALF_WORDS + q0 * SROW + cn];
            blo[1] = Bb[HALF_WORDS + q1 * SROW + cn];
#pragma unroll
            for (int mi = 0; mi < 2; mi++) {
                mma16816(acc[mi][ni], a[mi], bhi);
                mma16816(acc[mi][ni], a[mi], blo);
            }
        }
    }
}

// fp16 store: pack two adjacent cols into one half2 word (opt relu)
__device__ __forceinline__ void gemm_store16(float acc[2][8][4],
    const float* __restrict__ bias, uint32_t* __restrict__ C16,
    int M, int rowBase, int warp_m, int warp_n, int g, int tg, int relu)
{
    float bv[8][2];
#pragma unroll
    for (int ni = 0; ni < 8; ni++) {
        int cb = warp_n + ni * 8 + 2 * tg;
        bv[ni][0] = bias[cb];
        bv[ni][1] = bias[cb + 1];
    }
#pragma unroll
    for (int mi = 0; mi < 2; mi++) {
#pragma unroll
        for (int rh = 0; rh < 2; rh++) {
            int row = rowBase + warp_m + mi * 16 + g + rh * 8;
            if (row < M) {
#pragma unroll
                for (int ni = 0; ni < 8; ni++) {
                    float vx = acc[mi][ni][rh * 2 + 0] + bv[ni][0];
                    float vy = acc[mi][ni][rh * 2 + 1] + bv[ni][1];
                    if (relu) { vx = fmaxf(vx, 0.f); vy = fmaxf(vy, 0.f); }
                    int col = warp_n + ni * 8 + 2 * tg;
                    C16[(size_t)row * 64 + (col >> 1)] = pack_h2(vx, vy);
                }
            }
        }
    }
}

// Persistent single GEMM (input layer): h16 = relu(x @ W + b). B copied once.
__global__ __launch_bounds__(256) void pers_gemm(
    int M, const float* __restrict__ A, const uint32_t* __restrict__ Bimg,
    const float* __restrict__ bias, uint32_t* __restrict__ C16)
{
    extern __shared__ uint32_t sm[];
    uint32_t* Ah = sm;
    uint32_t* Bb = sm + HALF_WORDS;

    int tid = threadIdx.x;
    int warp = tid >> 5, lane = tid & 31;
    int g = lane >> 2, tg = lane & 3;
    int warp_m = (warp >> 1) * 32;
    int warp_n = (warp & 1) * 64;
    int ntiles = (M + 127) >> 7;

    gemm_copyB(Bb, Bimg, tid);

    for (int tile = blockIdx.x; tile < ntiles; tile += gridDim.x) {
        __syncthreads();
        gemm_cvtA_plain(Ah, A, M, tile * 128, tid);
        __syncthreads();
        float acc[2][8][4];
        gemm_compute(Ah, Bb, warp_m, warp_n, g, tg, acc);
        gemm_store16(acc, bias, C16, M, tile * 128, warp_m, warp_n, g, tg, 1);
    }
}

// ---------------------------------------------------------------------------
// Persistent dual GEMM: A16 (fp16) normalized inline, fused adot.
// Outputs m16 and pre16 (both fp16). In-place A16 == pre16 is safe.
// ---------------------------------------------------------------------------
__global__ __launch_bounds__(256) void pers_dual_gemm(
    int M, float invN, const uint32_t* __restrict__ A16, int useLN,
    const float* __restrict__ stats,
    const float* __restrict__ gamma, const float* __restrict__ beta,
    const float* __restrict__ Wa_l, float* __restrict__ a_out,
    const uint32_t* __restrict__ Bm_img, const uint32_t* __restrict__ Br_img,
    const float* __restrict__ bm, const float* __restrict__ br,
    uint32_t* __restrict__ Cm16, uint32_t* __restrict__ Cpre16)
{
    extern __shared__ uint32_t sm[];
    uint32_t* Ah  = sm;
    uint32_t* Bmb = sm + HALF_WORDS;
    uint32_t* Brb = sm + 3 * HALF_WORDS;
    __shared__ float s_scale[128], s_shift[128];
    __shared__ float s_ws[128], s_wd[128];
    __shared__ float s_pdS[2][128], s_pdD[2][128];

    int tid = threadIdx.x;
    int warp = tid >> 5, lane = tid & 31;
    int g = lane >> 2, tg = lane & 3;
    int warp_m = (warp >> 1) * 32;
    int warp_n = (warp & 1) * 64;
    int ntiles = (M + 127) >> 7;

    if (tid < 128) {
        float sc = 1.f, sh = 0.f;
        if (useLN) {
            float s = stats[tid], q = stats[128 + tid];
            float mu = s * invN;
            float var = q * invN - mu * mu;
            float rs = rsqrtf(var + EPSV);
            sc = rs * gamma[tid];
            sh = beta[tid] - mu * sc;
        }
        s_scale[tid] = sc;
        s_shift[tid] = sh;
        s_ws[tid] = Wa_l[tid];
        s_wd[tid] = Wa_l[128 + tid];
    }
    gemm_copyB(Bmb, Bm_img, tid);
    gemm_copyB(Brb, Br_img, tid);

    for (int tile = blockIdx.x; tile < ntiles; tile += gridDim.x) {
        int rowBase = tile * 128;
        __syncthreads();   // B/scale ready; prev iter compute + a_out done
        gemm_cvtA16(Ah, A16, M, rowBase, tid, s_scale, s_shift, s_ws, s_wd,
                    s_pdS, s_pdD);
        __syncthreads();
        if (tid < 128 && rowBase + tid < M) {
            a_out[2 * (rowBase + tid)]     = s_pdS[0][tid] + s_pdS[1][tid];
            a_out[2 * (rowBase + tid) + 1] = s_pdD[0][tid] + s_pdD[1][tid];
        }
        {
            float acc[2][8][4];
            gemm_compute(Ah, Bmb, warp_m, warp_n, g, tg, acc);
            gemm_store16(acc, bm, Cm16, M, rowBase, warp_m, warp_n, g, tg, 0);
        }
        {
            float acc[2][8][4];
            gemm_compute(Ah, Brb, warp_m, warp_n, g, tg, acc);
            gemm_store16(acc, br, Cpre16, M, rowBase, warp_m, warp_n, g, tg, 0);
        }
    }
}

// ---------------------------------------------------------------------------
// CSR build: scan + fill (count fused into prep_count_kernel)
// ---------------------------------------------------------------------------
#define SCB 4096   // elements per scan block (256 thr x 16)

__global__ __launch_bounds__(256) void scan1_kernel(int N) {
    __shared__ int wsum[8];
    int tid = threadIdx.x;
    int lane = tid & 31, w = tid >> 5;
    int base = blockIdx.x * SCB + tid * 16;
    int v[16];
    int s = 0;
#pragma unroll
    for (int i = 0; i < 16; i++) {
        int idx = base + i;
        v[i] = (idx < N) ? g_deg[idx] : 0;
        s += v[i];
    }
    int incl = s;
#pragma unroll
    for (int d = 1; d < 32; d <<= 1) {
        int t = __shfl_up_sync(0xFFFFFFFFu, incl, d);
        if (lane >= d) incl += t;
    }
    if (lane == 31) wsum[w] = incl;
    __syncthreads();
    if (tid == 0) {
        int c = 0;
#pragma unroll
        for (int i = 0; i < 8; i++) { int x = wsum[i]; wsum[i] = c; c += x; }
        g_btot[blockIdx.x] = c;
    }
    __syncthreads();
    int run = incl - s + wsum[w];
#pragma unroll
    for (int i = 0; i < 16; i++) {
        int idx = base + i;
        if (idx < N) g_off[idx] = run;
        run += v[i];
    }
}

// scan3: adds inline prefix of block totals (nb <= 13)
__global__ __launch_bounds__(256) void scan3_kernel(int N) {
    int i = blockIdx.x * 256 + threadIdx.x;
    if (i < N) {
        int b = i / SCB;
        int add = 0;
        for (int j = 0; j < b; j++) add += g_btot[j];
        int o = g_off[i] + add;
        g_off[i] = o;
        g_cursor[i] = o;
    }
}

__global__ __launch_bounds__(256) void fill_kernel(
    int E, const int* __restrict__ src, const int* __restrict__ dst)
{
    int i = blockIdx.x * 256 + threadIdx.x;
    if (i < E) {
        int slot = atomicAdd(&g_cursor[dst[i]], 1);
        g_adj[slot] = src[i];
    }
}

// ---------------------------------------------------------------------------
// Gather: pre16[d] += sum_in sigmoid(a_src[s]+a_dst[d]+ba)*m16[s]
// CSR, warp per row, 8/4-edge ILP batches. fp32 accumulate. Fused LN stats.
// ---------------------------------------------------------------------------
__global__ __launch_bounds__(256) void gather_kernel(
    int N, const float* __restrict__ a, const float* __restrict__ ba_l,
    const uint32_t* __restrict__ m16, uint32_t* __restrict__ pre16,
    float* __restrict__ stats)
{
    __shared__ float redS[8][128], redQ[8][128];
    int tid = threadIdx.x;
    int w = tid >> 5, lane = tid & 31;
    float bav = ba_l[0];
    float4 s1 = make_float4(0.f, 0.f, 0.f, 0.f);
    float4 s2 = make_float4(0.f, 0.f, 0.f, 0.f);
    const uint2* m2 = (const uint2*)m16;   // 32 uint2 per row
    uint2* p2 = (uint2*)pre16;

    for (int row = blockIdx.x * 8 + w; row < N; row += gridDim.x * 8) {
        uint2 pw = p2[(size_t)row * 32 + lane];
        float2 plo = unpack_h2(pw.x), phi = unpack_h2(pw.y);
        float4 v = make_float4(plo.x, plo.y, phi.x, phi.y);
        float ad = a[2 * row + 1] + bav;
        int off = g_off[row];
        int deg = g_deg[row];
        const int* ep = g_adj + off;

        int e = 0;
        // --- 8-edge batches ---
        for (; e + 8 <= deg; e += 8) {
            int sn[8]; float z[8]; uint2 mm[8];
#pragma unroll
            for (int j = 0; j < 8; j++) sn[j] = ep[e + j];
#pragma unroll
            for (int j = 0; j < 8; j++) z[j] = a[2 * sn[j]];
#pragma unroll
            for (int j = 0; j < 8; j++) mm[j] = m2[(size_t)sn[j] * 32 + lane];
#pragma unroll
            for (int j = 0; j < 8; j++) {
                float gt = 1.f / (1.f + __expf(-(z[j] + ad)));
                float2 lo = unpack_h2(mm[j].x), hi = unpack_h2(mm[j].y);
                v.x += gt * lo.x; v.y += gt * lo.y;
                v.z += gt * hi.x; v.w += gt * hi.y;
            }
        }
        // --- 4-edge batch ---
        if (e + 4 <= deg) {
            int sn[4]; float z[4]; uint2 mm[4];
#pragma unroll
            for (int j = 0; j < 4; j++) sn[j] = ep[e + j];
#pragma unroll
            for (int j = 0; j < 4; j++) z[j] = a[2 * sn[j]];
#pragma unroll
            for (int j = 0; j < 4; j++) mm[j] = m2[(size_t)sn[j] * 32 + lane];
#pragma unroll
            for (int j = 0; j < 4; j++) {
                float gt = 1.f / (1.f + __expf(-(z[j] + ad)));
                float2 lo = unpack_h2(mm[j].x), hi = unpack_h2(mm[j].y);
                v.x += gt * lo.x; v.y += gt * lo.y;
                v.z += gt * hi.x; v.w += gt * hi.y;
            }
            e += 4;
        }
        // --- remainder ---
        for (; e < deg; e++) {
            int sA = ep[e];
            float zA = a[2 * sA];
            uint2 mA = m2[(size_t)sA * 32 + lane];
            float gt = 1.f / (1.f + __expf(-(zA + ad)));
            float2 lo = unpack_h2(mA.x), hi = unpack_h2(mA.y);
            v.x += gt * lo.x; v.y += gt * lo.y;
            v.z += gt * hi.x; v.w += gt * hi.y;
        }

        uint2 ow;
        ow.x = pack_h2(v.x, v.y);
        ow.y = pack_h2(v.z, v.w);
        p2[(size_t)row * 32 + lane] = ow;
        s1.x += v.x; s1.y += v.y; s1.z += v.z; s1.w += v.w;
        s2.x += v.x * v.x; s2.y += v.y * v.y;
        s2.z += v.z * v.z; s2.w += v.w * v.w;
    }
    *(float4*)&redS[w][lane * 4] = s1;
    *(float4*)&redQ[w][lane * 4] = s2;
    __syncthreads();
    if (tid < 128) {
        float aa = 0.f, bb = 0.f;
#pragma unroll
        for (int i = 0; i < 8; i++) { aa += redS[i][tid]; bb += redQ[i][tid]; }
        atomicAdd(&stats[tid], aa);
        atomicAdd(&stats[128 + tid], bb);
    }
}

// ---------------------------------------------------------------------------
// Final pool: normalize pre16 (layer 3) on the fly and pool. Warp per row.
// Also restores g_deg = 0 (state invariant for the next call).
// ---------------------------------------------------------------------------
__global__ __launch_bounds__(256) void pool_kernel(
    int N, float invN, const uint32_t* __restrict__ pre16,
    const float* __restrict__ stats,
    const float* __restrict__ gamma, const float* __restrict__ beta,
    const int* __restrict__ batch, float* __restrict__ pool)
{
    int tid = threadIdx.x;
    int w = tid >> 5, lane = tid & 31;
    float sc[4], sh[4];
#pragma unroll
    for (int i = 0; i < 4; i++) {
        int c = lane * 4 + i;
        float s = stats[c], q = stats[128 + c];
        float mu = s * invN;
        float var = q * invN - mu * mu;
        float rs = rsqrtf(var + EPSV);
        sc[i] = rs * gamma[c];
        sh[i] = beta[c] - mu * sc[i];
    }
    const uint2* p2 = (const uint2*)pre16;
    for (int row = blockIdx.x * 8 + w; row < N; row += gridDim.x * 8) {
        uint2 pw = p2[(size_t)row * 32 + lane];
        float2 plo = unpack_h2(pw.x), phi = unpack_h2(pw.y);
        float4 v;
        v.x = fmaxf(plo.x * sc[0] + sh[0], 0.f);
        v.y = fmaxf(plo.y * sc[1] + sh[1], 0.f);
        v.z = fmaxf(phi.x * sc[2] + sh[2], 0.f);
        v.w = fmaxf(phi.y * sc[3] + sh[3], 0.f);
        int b = batch[row];
        atomicAdd(((float4*)(pool + (size_t)b * 128)) + lane, v);
        if (lane == 0) g_deg[row] = 0;     // restore invariant
    }
}

// ---------------------------------------------------------------------------
// MLP head; restores g_pool and g_stats to zero (state invariant).
// ---------------------------------------------------------------------------
__global__ __launch_bounds__(256) void head_kernel(
    float* __restrict__ pool,
    const float* __restrict__ W1, const float* __restrict__ b1,
    const float* __restrict__ W2, const float* __restrict__ b2,
    float* __restrict__ out, float* __restrict__ stats)
{
    __shared__ float sh[G * 64];
    int tid = threadIdx.x;
    for (int o = tid; o < G * 64; o += 256) {
        int g = o >> 6, j = o & 63;
        float s = b1[j];
        const float* pr = pool + g * 128;
#pragma unroll 4
        for (int k = 0; k < 128; k++) s += pr[k] * W1[k * 64 + j];
        sh[o] = fmaxf(s, 0.f);
    }
    __syncthreads();            // all reads of pool complete
    for (int o = tid; o < G * H; o += 256) pool[o] = 0.f;
    for (int o = tid; o < LYR * 2 * H; o += 256) stats[o] = 0.f;
    for (int o = tid; o < G * C; o += 256) {
        int g = o / C, c = o % C;
        float s = b2[c];
        const float* hr = sh + g * 64;
#pragma unroll 4
        for (int k = 0; k < 64; k++) s += hr[k] * W2[k * C + c];
        out[o] = s * 0.5f;   // /TEMP
    }
}

// ---------------------------------------------------------------------------
// Launch
// ---------------------------------------------------------------------------
extern "C" void kernel_launch(void* const* d_in, const int* in_sizes, int n_in,
                              void* d_out, int out_size)
{
    const float* x     = (const float*)d_in[0];
    const int*   ei    = (const int*)d_in[1];
    const int*   batch = (const int*)d_in[2];
    const float* W_in  = (const float*)d_in[3];
    const float* b_in  = (const float*)d_in[4];
    const float* Wa    = (const float*)d_in[5];
    const float* ba    = (const float*)d_in[6];
    const float* Wm    = (const float*)d_in[7];
    const float* bm    = (const float*)d_in[8];
    const float* Wr    = (const float*)d_in[9];
    const float* br    = (const float*)d_in[10];
    const float* gamma = (const float*)d_in[11];
    const float* beta  = (const float*)d_in[12];
    const float* W1    = (const float*)d_in[13];
    const float* b1    = (const float*)d_in[14];
    const float* W2    = (const float*)d_in[15];
    const float* b2    = (const float*)d_in[16];

    int N = in_sizes[0] / 128;
    int E = in_sizes[1] / 2;
    const int* src = ei;
    const int* dst = ei + E;

    cudaFuncSetAttribute(pers_gemm, cudaFuncAttributeMaxDynamicSharedMemorySize,
                         PERS1_SMEM);
    cudaFuncSetAttribute(pers_dual_gemm, cudaFuncAttributeMaxDynamicSharedMemorySize,
                         PERS2_SMEM);

    float *p_a, *p_pool, *p_stats;
    uint32_t *p_h16, *p_m16, *p_pre16, *p_B;
    cudaGetSymbolAddress((void**)&p_h16, g_h16);
    cudaGetSymbolAddress((void**)&p_m16, g_m16);
    cudaGetSymbolAddress((void**)&p_pre16, g_pre16);
    cudaGetSymbolAddress((void**)&p_a, g_a);
    cudaGetSymbolAddress((void**)&p_pool, g_pool);
    cudaGetSymbolAddress((void**)&p_stats, g_stats);
    cudaGetSymbolAddress((void**)&p_B, g_Bsplit);

    int rowBlocks = cdiv(N, 8);
    int scanBlocks = cdiv(N, SCB);
    int countBlocks = cdiv(E, 256);
    float invN = 1.0f / (float)N;

    // --- one-time per call: fused weights prep + count, then scan + fill ---
    prep_count_kernel<<<dim3(countBlocks, 10), 256>>>(W_in, Wm, Wr, E, dst);
    scan1_kernel<<<scanBlocks, 256>>>(N);
    scan3_kernel<<<cdiv(N, 256), 256>>>(N);
    fill_kernel<<<countBlocks, 256>>>(E, src, dst);

    // h16 = relu(x @ W_in + b_in)
    pers_gemm<<<GRID_PERS, 256, PERS1_SMEM>>>(N, x, p_B, b_in, p_h16);

    for (int l = 0; l < LYR; l++) {
        // A = (l==0) ? h16 (identity) : pre16 (inline LN+relu). Fused adot.
        pers_dual_gemm<<<GRID_PERS, 256, PERS2_SMEM>>>(
            N, invN,
            (l == 0) ? p_h16 : p_pre16, (l == 0) ? 0 : 1,
            p_stats + (l - 1) * 2 * H,
            gamma + (l - 1) * H, beta + (l - 1) * H,
            Wa + l * 2 * H, p_a,
            p_B + (1 + l) * BMAT_WORDS, p_B + (5 + l) * BMAT_WORDS,
            bm + l * H, br + l * H, p_m16, p_pre16);
        // pre16 += sum_in sigmoid(...)*m16[src]; fused LN stats
        gather_kernel<<<2048, 256>>>(N, p_a, ba + l, p_m16, p_pre16,
                                     p_stats + l * 2 * H);
    }

    // pool = segment_sum(LN(pre16_3)); restores g_deg
    pool_kernel<<<rowBlocks, 256>>>(N, invN, p_pre16, p_stats + 3 * 2 * H,
                                    gamma + 3 * H, beta + 3 * H, batch, p_pool);
    // head; restores g_pool/g_stats
    head_kernel<<<1, 256>>>(p_pool, W1, b1, W2, b2, (float*)d_out, p_stats);
}